// round 2
// baseline (speedup 1.0000x reference)
#include <cuda_runtime.h>
#include <math.h>

#define NF    64
#define NL    5
#define NMZI  2016
#define NCLS  12
#define TILE_R 128
#define TPB   256

#define CHALF 0.70710678118654752f
#define GAM   0.05f
#define GAM2  0.0025f

// field buffer row stride (in float2) — 65 => 520B rows, de-conflicts warp halves
#define FSTR  65

typedef unsigned long long u64;

// ---------------- packed f32x2 helpers ----------------
__device__ __forceinline__ u64 FMA2(u64 a, u64 b, u64 c) {
    u64 d;
    asm("fma.rn.f32x2 %0, %1, %2, %3;" : "=l"(d) : "l"(a), "l"(b), "l"(c));
    return d;
}
__device__ __forceinline__ u64 PK(float lo, float hi) {
    u64 r;
    asm("mov.b64 %0, {%1, %2};" : "=l"(r) : "f"(lo), "f"(hi));
    return r;
}
__device__ __forceinline__ void UPK(u64 v, float& lo, float& hi) {
    asm("mov.b64 {%0, %1}, %2;" : "=f"(lo), "=f"(hi) : "l"(v));
}

// scratch (device globals: allocation-free)
__device__ float4 g_trig[NL * NMZI];     // (cos th, sin th, cos phi, sin phi)
__device__ float4 g_UTdup[NL * NF * NF]; // [l][j][c] = (ux,ux,uy,uy), u = U[c][j] (phase applied)

// ---------------------------------------------------------------------------
__global__ void trig_kernel(const float* __restrict__ mzi) {
    int idx = blockIdx.x * blockDim.x + threadIdx.x;
    if (idx >= NL * NMZI) return;
    int l = idx / NMZI, k = idx - l * NMZI;
    float th = mzi[l * (2 * NMZI) + 2 * k];
    float ph = mzi[l * (2 * NMZI) + 2 * k + 1];
    float st, ct, sp, cp;
    sincosf(th, &st, &ct);
    sincosf(ph, &sp, &cp);
    g_trig[idx] = make_float4(ct, st, cp, sp);
}

// ---------------------------------------------------------------------------
// Build the 5 unitaries; one block per layer, thread t owns column t.
// ---------------------------------------------------------------------------
__global__ void build_unitaries(const float* __restrict__ ophase) {
    __shared__ float2 sU[NF * NF];       // sU[r*64 + c]
    const int l = blockIdx.x;
    const int t = threadIdx.x;           // column index
    for (int idx = t; idx < NF * NF; idx += 64) {
        int r = idx >> 6, c = idx & 63;
        sU[idx] = make_float2(r == c ? 1.f : 0.f, 0.f);
    }
    __syncthreads();

    int i = 0, j = 1;
    float2 ui = sU[t];
    const float4* trig = g_trig + l * NMZI;
    for (int k = 0; k < NMZI; ++k) {
        float4 tr = trig[k];             // ct, st, cp, sp
        float2 uj = sU[j * NF + t];
        float epx = tr.z * uj.x - tr.w * uj.y;
        float epy = tr.z * uj.y + tr.w * uj.x;
        float dx = ui.x - epx, dy = ui.y - epy;
        ui.x = CHALF * (ui.x + epx);
        ui.y = CHALF * (ui.y + epy);
        float2 nj;
        nj.x = CHALF * (tr.x * dx - tr.y * dy);
        nj.y = CHALF * (tr.y * dx + tr.x * dy);
        sU[j * NF + t] = nj;
        if (++j == NF) {
            sU[i * NF + t] = ui;
            ++i;
            j = i + 1;
            if (i < NF) ui = sU[i * NF + t];
        }
    }
    // apply output phases (row scaling), write duplicated transposed form
    for (int r = 0; r < NF; ++r) {
        float so, co;
        sincosf(ophase[l * NF + r], &so, &co);
        float2 v = sU[r * NF + t];
        float ux = co * v.x - so * v.y;
        float uy = co * v.y + so * v.x;
        g_UTdup[l * NF * NF + t * NF + r] = make_float4(ux, ux, uy, uy);
    }
}

// ---------------------------------------------------------------------------
// Fully fused main kernel. 128 rows/block, 256 threads.
// Complex GEMM: packed f32x2, two-accumulator scheme, zero swap MOVs.
// ---------------------------------------------------------------------------
// smem regions (bytes):
//   R0: 0      : field buf 128 x FSTR float2 (66560) / sPow,sH2 stride 68
//   R1: 66560  : Udup 64x64x16 (65536)             / sH1 stride 132 (67584)
//   R2: 134656 : weights (W1T 33792 / W2T 34816 / W3 3072)
#define SMEM_R1 66560
#define SMEM_R2 134656
#define SMEM_TOTAL (SMEM_R2 + 34816)

__global__ __launch_bounds__(TPB, 1)
void ficonn_main(const float* __restrict__ x,
                 const float* __restrict__ beta_param,
                 const float* __restrict__ det0,
                 const float* __restrict__ W1, const float* __restrict__ b1,
                 const float* __restrict__ W2, const float* __restrict__ b2,
                 const float* __restrict__ W3, const float* __restrict__ b3,
                 float* __restrict__ out)
{
    extern __shared__ char smem[];
    float2*     fb  = (float2*)smem;                 // field buffer, row stride FSTR
    ulonglong2* sU  = (ulonglong2*)(smem + SMEM_R1); // (UXX, UYY) per (j,c)
    float*      sWf = (float*)(smem + SMEM_R2);

    const int t  = threadIdx.x;
    const int rt = t >> 4;           // 0..15
    const int ct = t & 15;           // 0..15
    const int r0 = rt * 8;
    const int c0 = ct * 4;
    const long base = (long)blockIdx.x * TILE_R;

    // ---- load x tile (imag = 0), vectorized global reads ----
    {
        const float4* xv = (const float4*)(x + base * NF);
        for (int idx = t; idx < TILE_R * (NF / 4); idx += TPB) {
            int r = idx >> 4, c4 = (idx & 15) * 4;
            float4 v = xv[idx];
            float2* row = fb + r * FSTR + c4;
            row[0] = make_float2(v.x, 0.f);
            row[1] = make_float2(v.y, 0.f);
            row[2] = make_float2(v.z, 0.f);
            row[3] = make_float2(v.w, 0.f);
        }
    }
    // ---- load Udup layer 0 ----
    {
        const float4* gu = (const float4*)g_UTdup;
        float4* su = (float4*)sU;
        for (int idx = t; idx < NF * NF; idx += TPB) su[idx] = gu[idx];
    }

    for (int l = 0; l < NL; ++l) {
        __syncthreads();   // field + U ready

        u64 acc1[8][4], acc2[8][4];
        #pragma unroll
        for (int p = 0; p < 8; ++p)
            #pragma unroll
            for (int q = 0; q < 4; ++q) { acc1[p][q] = 0ULL; acc2[p][q] = 0ULL; }

        #pragma unroll 2
        for (int j = 0; j < NF; ++j) {
            ulonglong2 U[4];
            #pragma unroll
            for (int q = 0; q < 4; ++q) U[q] = sU[j * NF + c0 + q];
            #pragma unroll
            for (int p = 0; p < 8; ++p) {
                const u64 F = *(const u64*)(fb + (r0 + p) * FSTR + j); // (fx,fy)
                #pragma unroll
                for (int q = 0; q < 4; ++q) {
                    acc1[p][q] = FMA2(U[q].x, F, acc1[p][q]); // (+ux*fx, +ux*fy)
                    acc2[p][q] = FMA2(U[q].y, F, acc2[p][q]); // (+uy*fx, +uy*fy)
                }
            }
        }

        __syncthreads();   // all reads of fb/sU done

        if (l < NL - 1) {
            // ---- nofu nonlinearity, write back in place ----
            float sqq[4], kkq[4], d0q[4];
            #pragma unroll
            for (int q = 0; q < 4; ++q) {
                int c = c0 + q;
                float bp   = beta_param[l * NF + c];
                float beta = 1.f / (1.f + expf(-bp));
                sqq[q] = sqrtf(fmaxf(1.f - beta, 0.f));
                kkq[q] = 0.001f * 0.8f * beta;
                d0q[q] = det0[l * NF + c];
            }
            #pragma unroll
            for (int p = 0; p < 8; ++p) {
                #pragma unroll
                for (int q = 0; q < 4; ++q) {
                    float a1l, a1h, a2l, a2h;
                    UPK(acc1[p][q], a1l, a1h);
                    UPK(acc2[p][q], a2l, a2h);
                    float fx = a1l - a2h;   // re
                    float fy = a1h + a2l;   // im
                    float pw = fx * fx + fy * fy;
                    float det = fmaf(kkq[q], pw, d0q[q]);
                    float s = sqq[q] * GAM / fmaf(det, det, GAM2);
                    float ox = s * fmaf(fy, det, fx * GAM);
                    float oy = s * fmaf(-fx, det, fy * GAM);
                    fb[(r0 + p) * FSTR + c0 + q] = make_float2(ox, oy);
                }
            }
            // load next layer's Udup
            const float4* gu = (const float4*)(g_UTdup + (l + 1) * NF * NF);
            float4* su = (float4*)sU;
            for (int idx = t; idx < NF * NF; idx += TPB) su[idx] = gu[idx];
        } else {
            // ---- final |field|^2 -> power plane (stride 68, region R0) ----
            float* sPow = (float*)smem;
            #pragma unroll
            for (int p = 0; p < 8; ++p) {
                #pragma unroll
                for (int q = 0; q < 4; ++q) {
                    float a1l, a1h, a2l, a2h;
                    UPK(acc1[p][q], a1l, a1h);
                    UPK(acc2[p][q], a2l, a2h);
                    float fx = a1l - a2h;
                    float fy = a1h + a2l;
                    sPow[(r0 + p) * 68 + c0 + q] = fx * fx + fy * fy;
                }
            }
        }
    }

    // ================= MLP head =================
    float* sPow = (float*)smem;              // 128 x 64, stride 68
    float* sH1  = (float*)(smem + SMEM_R1);  // 128 x 128, stride 132

    // W1 (128x64) -> transposed padded: sWf[j*132 + m]
    for (int idx = t; idx < 128 * 64; idx += TPB) {
        int m = idx >> 6, j = idx & 63;
        sWf[j * 132 + m] = W1[idx];
    }
    __syncthreads();

    // GEMM1: h1[r][m] = relu(b1[m] + sum_j P[r][j] * W1[m][j])
    // thread tile: 8 rows x 8 cols, cols m = 2*ct + 32*k + {0,1}, k=0..3  (packed pairs)
    {
        u64 acc[8][4];
        #pragma unroll
        for (int p = 0; p < 8; ++p)
            #pragma unroll
            for (int k = 0; k < 4; ++k) acc[p][k] = 0ULL;

        const int mb = 2 * ct;
        #pragma unroll 2
        for (int j = 0; j < 64; ++j) {
            u64 w[4];
            #pragma unroll
            for (int k = 0; k < 4; ++k)
                w[k] = *(const u64*)(sWf + j * 132 + mb + 32 * k);
            #pragma unroll
            for (int p = 0; p < 8; ++p) {
                float pv = sPow[(r0 + p) * 68 + j];
                u64 PV = PK(pv, pv);
                #pragma unroll
                for (int k = 0; k < 4; ++k) acc[p][k] = FMA2(PV, w[k], acc[p][k]);
            }
        }
        float bb0[4], bb1[4];
        #pragma unroll
        for (int k = 0; k < 4; ++k) { bb0[k] = b1[mb + 32 * k]; bb1[k] = b1[mb + 32 * k + 1]; }
        #pragma unroll
        for (int p = 0; p < 8; ++p) {
            #pragma unroll
            for (int k = 0; k < 4; ++k) {
                float lo, hi;
                UPK(acc[p][k], lo, hi);
                float2 o = make_float2(fmaxf(lo + bb0[k], 0.f), fmaxf(hi + bb1[k], 0.f));
                *(float2*)(sH1 + (r0 + p) * 132 + mb + 32 * k) = o;
            }
        }
    }
    __syncthreads();

    // W2 (64x128) -> transposed padded: sWf[m*68 + n]
    for (int idx = t; idx < 64 * 128; idx += TPB) {
        int n = idx >> 7, m = idx & 127;
        sWf[m * 68 + n] = W2[idx];
    }
    __syncthreads();

    // GEMM2: h2[r][n] = relu(b2[n] + sum_m h1[r][m] * W2[n][m])
    // thread tile: 8 rows x 4 cols, n = 2*ct + 32*k + {0,1}, k=0..1
    float* sH2 = sPow;   // reuse region R0, stride 68
    {
        u64 acc[8][2];
        #pragma unroll
        for (int p = 0; p < 8; ++p) { acc[p][0] = 0ULL; acc[p][1] = 0ULL; }

        const int nb = 2 * ct;
        #pragma unroll 2
        for (int m = 0; m < 128; ++m) {
            u64 w0 = *(const u64*)(sWf + m * 68 + nb);
            u64 w1 = *(const u64*)(sWf + m * 68 + nb + 32);
            #pragma unroll
            for (int p = 0; p < 8; ++p) {
                float hv = sH1[(r0 + p) * 132 + m];
                u64 HV = PK(hv, hv);
                acc[p][0] = FMA2(HV, w0, acc[p][0]);
                acc[p][1] = FMA2(HV, w1, acc[p][1]);
            }
        }
        float bb0[2] = {b2[nb], b2[nb + 32]};
        float bb1[2] = {b2[nb + 1], b2[nb + 33]};
        __syncthreads();  // all GEMM2 reads of sH1/sW2 done before overwriting sH2(=sPow)? sH2 is R0 — GEMM2 read sPow? No: GEMM2 reads sH1(R1)+sWf(R2). But sH2 overwrites sPow(R0) which GEMM1 read — GEMM1 finished at previous sync. Safe; this sync orders the sH2 writes for GEMM3 loads of W3 region too.
        #pragma unroll
        for (int p = 0; p < 8; ++p) {
            #pragma unroll
            for (int k = 0; k < 2; ++k) {
                float lo, hi;
                UPK(acc[p][k], lo, hi);
                float2 o = make_float2(fmaxf(lo + bb0[k], 0.f), fmaxf(hi + bb1[k], 0.f));
                *(float2*)(sH2 + (r0 + p) * 68 + nb + 32 * k) = o;
            }
        }
    }

    // W3 (12x64) into weight region (overwrites W2T — GEMM2 reads done after sync below)
    __syncthreads();
    for (int idx = t; idx < NCLS * 64; idx += TPB) sWf[idx] = W3[idx];
    __syncthreads();

    // GEMM3: out[r][c] = b3[c] + sum_j h2[r][j] * W3[c][j]
    {
        const int r  = t >> 1;
        const int ch = (t & 1) * 6;
        float acc[6] = {0.f, 0.f, 0.f, 0.f, 0.f, 0.f};
        #pragma unroll 4
        for (int j = 0; j < 64; ++j) {
            float h = sH2[r * 68 + j];
            #pragma unroll
            for (int q = 0; q < 6; ++q)
                acc[q] = fmaf(h, sWf[(ch + q) * 64 + j], acc[q]);
        }
        #pragma unroll
        for (int q = 0; q < 6; ++q)
            out[(base + r) * NCLS + ch + q] = acc[q] + b3[ch + q];
    }
}

// ---------------------------------------------------------------------------
extern "C" void kernel_launch(void* const* d_in, const int* in_sizes, int n_in,
                              void* d_out, int out_size) {
    const float* x     = (const float*)d_in[0];
    const float* mzi   = (const float*)d_in[1];
    const float* oph   = (const float*)d_in[2];
    const float* betap = (const float*)d_in[3];
    const float* det0  = (const float*)d_in[4];
    const float* W1    = (const float*)d_in[5];
    const float* b1    = (const float*)d_in[6];
    const float* W2    = (const float*)d_in[7];
    const float* b2    = (const float*)d_in[8];
    const float* W3    = (const float*)d_in[9];
    const float* b3    = (const float*)d_in[10];
    float* out = (float*)d_out;

    const int rows = in_sizes[0] / NF;          // 262144
    const int grid = rows / TILE_R;             // 2048

    cudaFuncSetAttribute(ficonn_main, cudaFuncAttributeMaxDynamicSharedMemorySize, SMEM_TOTAL);

    trig_kernel<<<(NL * NMZI + 255) / 256, 256>>>(mzi);
    build_unitaries<<<NL, 64>>>(oph);
    ficonn_main<<<grid, TPB, SMEM_TOTAL>>>(x, betap, det0, W1, b1, W2, b2, W3, b3, out);
}

// round 4
// speedup vs baseline: 2.5103x; 2.5103x over previous
#include <cuda_runtime.h>
#include <math.h>

#define NF    64
#define NL    5
#define NMZI  2016
#define NCLS  12
#define TILE_R 128
#define TPB   256

#define CHALF 0.70710678118654752f
#define GAM   0.05f
#define GAM2  0.0025f

typedef unsigned int u32;
typedef unsigned short u16;

// strides (in u16 elements / 32-bit words)
#define ASTR   136      // A row stride, bf16 elems (K<=128 + pad 8)
#define ASTRW  68       // in 32-bit words
#define BSTRW  68       // layer/W2 B^T row stride in words (136 bf16)
#define W1STRW 36       // W1 B^T row stride in words (72 bf16)

// smem layout (bytes)
#define OFF_AH 0
#define OFF_AL 34816
#define OFF_BH 69632                 // B region, 69632 bytes total
#define OFF_BL (OFF_BH + 34816)
#define OFF_H2 139264                // 128 x 68 fp32 = 34816
#define OFF_PAR 174080               // 64 x float4
#define OFF_B1 175104                // 128 f32
#define OFF_B2 175616                // 64 f32
#define SMEM_TOTAL 175872

// device global staging (allocation-free)
__device__ float4 g_trig[NL * NMZI];
__device__ __align__(16) u16 g_Bu[NL * 2 * 128 * ASTR];   // per layer: hi plane, lo plane (B^T)
__device__ __align__(16) u16 g_Bw1[2 * 128 * 72];         // W1 hi/lo (stride 72)
__device__ __align__(16) u16 g_Bw2[2 * 64 * ASTR];        // W2 hi/lo (stride 136)

// ---------------- helpers ----------------
__device__ __forceinline__ u16 f2bf(float f) {
    u16 h; asm("cvt.rn.bf16.f32 %0, %1;" : "=h"(h) : "f"(f)); return h;
}
__device__ __forceinline__ u16 f2bf_hi(float f, float& fh) {
    u16 h; asm("cvt.rn.bf16.f32 %0, %1;" : "=h"(h) : "f"(f));
    fh = __uint_as_float(((u32)h) << 16); return h;
}
__device__ __forceinline__ void mma_bf16(float* d, const u32* a, const u32* b) {
    asm volatile(
        "mma.sync.aligned.m16n8k16.row.col.f32.bf16.bf16.f32 "
        "{%0,%1,%2,%3},{%4,%5,%6,%7},{%8,%9},{%0,%1,%2,%3};"
        : "+f"(d[0]), "+f"(d[1]), "+f"(d[2]), "+f"(d[3])
        : "r"(a[0]), "r"(a[1]), "r"(a[2]), "r"(a[3]), "r"(b[0]), "r"(b[1]));
}

// ---------------------------------------------------------------------------
__global__ void trig_kernel(const float* __restrict__ mzi) {
    int idx = blockIdx.x * blockDim.x + threadIdx.x;
    if (idx >= NL * NMZI) return;
    int l = idx / NMZI, k = idx - l * NMZI;
    float th = mzi[l * (2 * NMZI) + 2 * k];
    float ph = mzi[l * (2 * NMZI) + 2 * k + 1];
    float st, ct, sp, cp;
    sincosf(th, &st, &ct);
    sincosf(ph, &sp, &cp);
    g_trig[idx] = make_float4(ct, st, cp, sp);
}

// ---------------------------------------------------------------------------
// Build unitaries; emit B^T planes (bf16 hi/lo).
// Layer 0 (K=64):    B^T[2c+0][j]    = Ur(c,j),  B^T[2c+1][j]    = Ui(c,j)
// Layers 1..4 (K=128, interleaved):
//   B^T[2c][2j]=Ur, B^T[2c][2j+1]=-Ui, B^T[2c+1][2j]=Ui, B^T[2c+1][2j+1]=Ur
// ---------------------------------------------------------------------------
__global__ void build_unitaries(const float* __restrict__ ophase) {
    __shared__ float2 sU[NF * NF];
    __shared__ float sco[NF], ssi[NF];
    const int l = blockIdx.x;
    const int t = threadIdx.x;   // column j
    for (int idx = t; idx < NF * NF; idx += 64) {
        int r = idx >> 6, c = idx & 63;
        sU[idx] = make_float2(r == c ? 1.f : 0.f, 0.f);
    }
    {
        float s, c; sincosf(ophase[l * NF + t], &s, &c);
        sco[t] = c; ssi[t] = s;
    }
    __syncthreads();

    int i = 0, j = 1;
    float2 ui = sU[t];
    const float4* trig = g_trig + l * NMZI;
    for (int k = 0; k < NMZI; ++k) {
        float4 tr = trig[k];
        float2 uj = sU[j * NF + t];
        float epx = tr.z * uj.x - tr.w * uj.y;
        float epy = tr.z * uj.y + tr.w * uj.x;
        float dx = ui.x - epx, dy = ui.y - epy;
        ui.x = CHALF * (ui.x + epx);
        ui.y = CHALF * (ui.y + epy);
        float2 nj;
        nj.x = CHALF * (tr.x * dx - tr.y * dy);
        nj.y = CHALF * (tr.y * dx + tr.x * dy);
        sU[j * NF + t] = nj;
        if (++j == NF) {
            sU[i * NF + t] = ui;
            ++i; j = i + 1;
            if (i < NF) ui = sU[i * NF + t];
        }
    }
    __syncthreads();

    u16* hi = g_Bu + l * 2 * 128 * ASTR;
    u16* lo = hi + 128 * ASTR;
    for (int r = 0; r < NF; ++r) {
        float co = sco[r], si = ssi[r];
        float2 v = sU[r * NF + t];
        float ur = co * v.x - si * v.y;
        float um = co * v.y + si * v.x;
        float fh;
        u16 urh = f2bf_hi(ur, fh); u16 url = f2bf(ur - fh);
        u16 uih = f2bf_hi(um, fh); u16 uil = f2bf(um - fh);
        if (l == 0) {
            hi[(2 * r) * ASTR + t] = urh;     lo[(2 * r) * ASTR + t] = url;
            hi[(2 * r + 1) * ASTR + t] = uih; lo[(2 * r + 1) * ASTR + t] = uil;
        } else {
            hi[(2 * r) * ASTR + 2 * t]     = urh;           lo[(2 * r) * ASTR + 2 * t]     = url;
            hi[(2 * r) * ASTR + 2 * t + 1] = uih ^ 0x8000;  lo[(2 * r) * ASTR + 2 * t + 1] = uil ^ 0x8000;
            hi[(2 * r + 1) * ASTR + 2 * t]     = uih;       lo[(2 * r + 1) * ASTR + 2 * t]     = uil;
            hi[(2 * r + 1) * ASTR + 2 * t + 1] = urh;       lo[(2 * r + 1) * ASTR + 2 * t + 1] = url;
        }
    }
}

// ---------------------------------------------------------------------------
__global__ void prep_mlp(const float* __restrict__ W1, const float* __restrict__ W2) {
    int idx = blockIdx.x * blockDim.x + threadIdx.x;
    if (idx < 8192) {
        int m = idx >> 6, j = idx & 63;
        float v = W1[idx];
        float fh; u16 h = f2bf_hi(v, fh); u16 lo = f2bf(v - fh);
        g_Bw1[m * 72 + j] = h;
        g_Bw1[128 * 72 + m * 72 + j] = lo;
    } else if (idx < 16384) {
        int i2 = idx - 8192;
        int n = i2 >> 7, m = i2 & 127;
        float v = W2[i2];
        float fh; u16 h = f2bf_hi(v, fh); u16 lo = f2bf(v - fh);
        g_Bw2[n * ASTR + m] = h;
        g_Bw2[64 * ASTR + n * ASTR + m] = lo;
    }
}

// ---------------------------------------------------------------------------
// Main fused kernel: mma.sync bf16x3.
// ---------------------------------------------------------------------------
__global__ __launch_bounds__(TPB, 1)
void ficonn_main(const float* __restrict__ x,
                 const float* __restrict__ beta_param,
                 const float* __restrict__ det0,
                 const float* __restrict__ b1,
                 const float* __restrict__ b2,
                 const float* __restrict__ W3, const float* __restrict__ b3,
                 float* __restrict__ out)
{
    extern __shared__ char smem[];
    const int t = threadIdx.x;
    const int wid = t >> 5;
    const int lane = t & 31;
    const int g = lane >> 2;     // groupID
    const int q = lane & 3;      // quad lane
    const long base = (long)blockIdx.x * TILE_R;

    u32* pAH = (u32*)(smem + OFF_AH);
    u32* pAL = (u32*)(smem + OFF_AL);
    float4* sPar = (float4*)(smem + OFF_PAR);
    float*  sB1  = (float*)(smem + OFF_B1);
    float*  sB2  = (float*)(smem + OFF_B2);
    float*  sH2  = (float*)(smem + OFF_H2);

    // warp grid for N=128 GEMMs: 4(M) x 2(N)
    const int m0 = (wid >> 1) * 32;
    const int n0 = (wid & 1) * 64;

    // ---- init: x -> A planes, layer-0 layout (K=64, cols 0..63) ----
    {
        const float4* xv = (const float4*)(x + base * NF);
        for (int idx = t; idx < TILE_R * (NF / 4); idx += TPB) {
            int r = idx >> 4, c4 = (idx & 15) * 4;
            float4 v = xv[idx];
            float f0, f1, f2, f3;
            u16 h0 = f2bf_hi(v.x, f0), h1 = f2bf_hi(v.y, f1);
            u16 h2 = f2bf_hi(v.z, f2), h3 = f2bf_hi(v.w, f3);
            int w = r * ASTRW + (c4 >> 1);
            *(uint2*)(pAH + w) = make_uint2((u32)h0 | ((u32)h1 << 16), (u32)h2 | ((u32)h3 << 16));
            *(uint2*)(pAL + w) = make_uint2(
                (u32)f2bf(v.x - f0) | ((u32)f2bf(v.y - f1) << 16),
                (u32)f2bf(v.z - f2) | ((u32)f2bf(v.w - f3) << 16));
        }
        if (t < 128) sB1[t] = b1[t];
        else if (t < 192) sB2[t - 128] = b2[t - 128];
    }

    // ================= photonic layers =================
    for (int l = 0; l < NL; ++l) {
        // stage B planes for this layer (69632 B)
        {
            const uint4* gB = (const uint4*)(g_Bu + l * 2 * 128 * ASTR);
            uint4* dB = (uint4*)(smem + OFF_BH);
            #pragma unroll
            for (int i = 0; i < 17; ++i) dB[t + i * TPB] = gB[t + i * TPB];
        }
        if (l < NL - 1 && t < 64) {
            float bp = beta_param[l * NF + t];
            float beta = 1.f / (1.f + expf(-bp));
            float sgam = sqrtf(fmaxf(1.f - beta, 0.f)) * GAM;
            sPar[t] = make_float4(sgam, 0.0008f * beta, det0[l * NF + t], 0.f);
        }
        __syncthreads();

        const u32* pBH = (const u32*)(smem + OFF_BH);
        const u32* pBL = (const u32*)(smem + OFF_BL);

        float acc[2][8][4];
        #pragma unroll
        for (int mt = 0; mt < 2; ++mt)
            #pragma unroll
            for (int nt = 0; nt < 8; ++nt)
                #pragma unroll
                for (int e = 0; e < 4; ++e) acc[mt][nt][e] = 0.f;

        const int kmax = (l == 0) ? 4 : 8;
        for (int kk = 0; kk < kmax; ++kk) {
            u32 ah[2][4], al[2][4], bh[8][2], bl[8][2];
            #pragma unroll
            for (int mt = 0; mt < 2; ++mt) {
                int w = (m0 + mt * 16 + g) * ASTRW + kk * 8 + q;
                ah[mt][0] = pAH[w]; ah[mt][1] = pAH[w + 8 * ASTRW];
                ah[mt][2] = pAH[w + 4]; ah[mt][3] = pAH[w + 8 * ASTRW + 4];
            }
            #pragma unroll
            for (int nt = 0; nt < 8; ++nt) {
                int w = (n0 + nt * 8 + g) * BSTRW + kk * 8 + q;
                bh[nt][0] = pBH[w]; bh[nt][1] = pBH[w + 4];
            }
            #pragma unroll
            for (int mt = 0; mt < 2; ++mt)
                #pragma unroll
                for (int nt = 0; nt < 8; ++nt) mma_bf16(acc[mt][nt], ah[mt], bh[nt]);
            #pragma unroll
            for (int nt = 0; nt < 8; ++nt) {
                int w = (n0 + nt * 8 + g) * BSTRW + kk * 8 + q;
                bl[nt][0] = pBL[w]; bl[nt][1] = pBL[w + 4];
            }
            #pragma unroll
            for (int mt = 0; mt < 2; ++mt)
                #pragma unroll
                for (int nt = 0; nt < 8; ++nt) mma_bf16(acc[mt][nt], ah[mt], bl[nt]);
            #pragma unroll
            for (int mt = 0; mt < 2; ++mt) {
                int w = (m0 + mt * 16 + g) * ASTRW + kk * 8 + q;
                al[mt][0] = pAL[w]; al[mt][1] = pAL[w + 8 * ASTRW];
                al[mt][2] = pAL[w + 4]; al[mt][3] = pAL[w + 8 * ASTRW + 4];
            }
            #pragma unroll
            for (int mt = 0; mt < 2; ++mt)
                #pragma unroll
                for (int nt = 0; nt < 8; ++nt) mma_bf16(acc[mt][nt], al[mt], bh[nt]);
        }
        __syncthreads();   // all smem reads done

        if (l < NL - 1) {
            // nofu epilogue; write A interleaved (K=128) for next layer
            #pragma unroll
            for (int mt = 0; mt < 2; ++mt) {
                #pragma unroll
                for (int nt = 0; nt < 8; ++nt) {
                    int c = (n0 >> 1) + nt * 4 + q;
                    float4 pr = sPar[c];
                    #pragma unroll
                    for (int h = 0; h < 2; ++h) {
                        int row = m0 + mt * 16 + g + h * 8;
                        float fx = acc[mt][nt][2 * h];
                        float fy = acc[mt][nt][2 * h + 1];
                        float pw = fx * fx + fy * fy;
                        float det = fmaf(pr.y, pw, pr.z);
                        float s = pr.x * __fdividef(1.f, fmaf(det, det, GAM2));
                        float ox = s * fmaf(fy, det, fx * GAM);
                        float oy = s * fmaf(-fx, det, fy * GAM);
                        float fa, fb;
                        u16 xh = f2bf_hi(ox, fa), yh = f2bf_hi(oy, fb);
                        int w = row * ASTRW + c;
                        pAH[w] = (u32)xh | ((u32)yh << 16);
                        pAL[w] = (u32)f2bf(ox - fa) | ((u32)f2bf(oy - fb) << 16);
                    }
                }
            }
        } else {
            // |field|^2 -> P in A layer-0 layout (K=64)
            u16* hAH = (u16*)(smem + OFF_AH);
            u16* hAL = (u16*)(smem + OFF_AL);
            #pragma unroll
            for (int mt = 0; mt < 2; ++mt) {
                #pragma unroll
                for (int nt = 0; nt < 8; ++nt) {
                    int c = (n0 >> 1) + nt * 4 + q;
                    #pragma unroll
                    for (int h = 0; h < 2; ++h) {
                        int row = m0 + mt * 16 + g + h * 8;
                        float fx = acc[mt][nt][2 * h];
                        float fy = acc[mt][nt][2 * h + 1];
                        float pw = fx * fx + fy * fy;
                        float fa; u16 ph = f2bf_hi(pw, fa);
                        hAH[row * ASTR + c] = ph;
                        hAL[row * ASTR + c] = f2bf(pw - fa);
                    }
                }
            }
        }
        __syncthreads();   // A writes visible before next layer reads / next B overwrite? (B overwritten next iter after this sync + its own pre-mma sync)
    }

    // ================= GEMM1: h1 = relu(P @ W1^T + b1), M=128 N=128 K=64 =================
    {
        const uint4* gB = (const uint4*)g_Bw1;
        uint4* dB = (uint4*)(smem + OFF_BH);
        for (int i = t; i < 36864 / 16; i += TPB) dB[i] = gB[i];
    }
    __syncthreads();
    {
        const u32* pBH = (const u32*)(smem + OFF_BH);
        const u32* pBL = (const u32*)(smem + OFF_BH + 18432);

        float acc[2][8][4];
        #pragma unroll
        for (int mt = 0; mt < 2; ++mt)
            #pragma unroll
            for (int nt = 0; nt < 8; ++nt)
                #pragma unroll
                for (int e = 0; e < 4; ++e) acc[mt][nt][e] = 0.f;

        for (int kk = 0; kk < 4; ++kk) {
            u32 ah[2][4], al[2][4], bh[8][2], bl[8][2];
            #pragma unroll
            for (int mt = 0; mt < 2; ++mt) {
                int w = (m0 + mt * 16 + g) * ASTRW + kk * 8 + q;
                ah[mt][0] = pAH[w]; ah[mt][1] = pAH[w + 8 * ASTRW];
                ah[mt][2] = pAH[w + 4]; ah[mt][3] = pAH[w + 8 * ASTRW + 4];
                al[mt][0] = pAL[w]; al[mt][1] = pAL[w + 8 * ASTRW];
                al[mt][2] = pAL[w + 4]; al[mt][3] = pAL[w + 8 * ASTRW + 4];
            }
            #pragma unroll
            for (int nt = 0; nt < 8; ++nt) {
                int w = (n0 + nt * 8 + g) * W1STRW + kk * 8 + q;
                bh[nt][0] = pBH[w]; bh[nt][1] = pBH[w + 4];
                bl[nt][0] = pBL[w]; bl[nt][1] = pBL[w + 4];
            }
            #pragma unroll
            for (int mt = 0; mt < 2; ++mt)
                #pragma unroll
                for (int nt = 0; nt < 8; ++nt) {
                    mma_bf16(acc[mt][nt], ah[mt], bh[nt]);
                    mma_bf16(acc[mt][nt], ah[mt], bl[nt]);
                    mma_bf16(acc[mt][nt], al[mt], bh[nt]);
                }
        }
        __syncthreads();   // P reads + W1 reads done

        // epilogue: relu+bias, write h1 into A planes (K=128 layout); stage W2
        {
            const uint4* gB = (const uint4*)g_Bw2;
            uint4* dB = (uint4*)(smem + OFF_BH);
            for (int i = t; i < 34816 / 16; i += TPB) dB[i] = gB[i];
        }
        #pragma unroll
        for (int mt = 0; mt < 2; ++mt) {
            #pragma unroll
            for (int nt = 0; nt < 8; ++nt) {
                int col = n0 + nt * 8 + q * 2;
                float bb0 = sB1[col], bb1 = sB1[col + 1];
                #pragma unroll
                for (int h = 0; h < 2; ++h) {
                    int row = m0 + mt * 16 + g + h * 8;
                    float v0 = fmaxf(acc[mt][nt][2 * h] + bb0, 0.f);
                    float v1 = fmaxf(acc[mt][nt][2 * h + 1] + bb1, 0.f);
                    float fa, fb;
                    u16 h0 = f2bf_hi(v0, fa), h1v = f2bf_hi(v1, fb);
                    int w = row * ASTRW + (col >> 1);
                    pAH[w] = (u32)h0 | ((u32)h1v << 16);
                    pAL[w] = (u32)f2bf(v0 - fa) | ((u32)f2bf(v1 - fb) << 16);
                }
            }
        }
    }
    __syncthreads();

    // ================= GEMM2: h2 = relu(h1 @ W2^T + b2), M=128 N=64 K=128 ===========
    // warp tile 16 x 64: wid -> 16-row band
    {
        const u32* pBH = (const u32*)(smem + OFF_BH);
        const u32* pBL = (const u32*)(smem + OFF_BH + 17408);
        const int mb = wid * 16;

        float acc[8][4];
        #pragma unroll
        for (int nt = 0; nt < 8; ++nt)
            #pragma unroll
            for (int e = 0; e < 4; ++e) acc[nt][e] = 0.f;

        for (int kk = 0; kk < 8; ++kk) {
            u32 ah[4], al[4], bh[8][2], bl[8][2];
            {
                int w = (mb + g) * ASTRW + kk * 8 + q;
                ah[0] = pAH[w]; ah[1] = pAH[w + 8 * ASTRW];
                ah[2] = pAH[w + 4]; ah[3] = pAH[w + 8 * ASTRW + 4];
                al[0] = pAL[w]; al[1] = pAL[w + 8 * ASTRW];
                al[2] = pAL[w + 4]; al[3] = pAL[w + 8 * ASTRW + 4];
            }
            #pragma unroll
            for (int nt = 0; nt < 8; ++nt) {
                int w = (nt * 8 + g) * BSTRW + kk * 8 + q;
                bh[nt][0] = pBH[w]; bh[nt][1] = pBH[w + 4];
                bl[nt][0] = pBL[w]; bl[nt][1] = pBL[w + 4];
            }
            #pragma unroll
            for (int nt = 0; nt < 8; ++nt) {
                mma_bf16(acc[nt], ah, bh[nt]);
                mma_bf16(acc[nt], ah, bl[nt]);
                mma_bf16(acc[nt], al, bh[nt]);
            }
        }
        __syncthreads();   // h1/W2 reads done

        // stage W3 into B region (free now)
        {
            float* sW3 = (float*)(smem + OFF_BH);
            for (int i = t; i < NCLS * 64; i += TPB) sW3[i] = W3[i];
        }
        // epilogue -> sH2 fp32 (stride 68)
        #pragma unroll
        for (int nt = 0; nt < 8; ++nt) {
            int col = nt * 8 + q * 2;
            float bb0 = sB2[col], bb1 = sB2[col + 1];
            #pragma unroll
            for (int h = 0; h < 2; ++h) {
                int row = mb + g + h * 8;
                sH2[row * 68 + col]     = fmaxf(acc[nt][2 * h] + bb0, 0.f);
                sH2[row * 68 + col + 1] = fmaxf(acc[nt][2 * h + 1] + bb1, 0.f);
            }
        }
    }
    __syncthreads();

    // ================= GEMM3 (scalar): out = h2 @ W3^T + b3 =================
    {
        const float* sW3 = (const float*)(smem + OFF_BH);
        const int rr = t >> 1;
        const int ch = (t & 1) * 6;
        float acc[6] = {0.f, 0.f, 0.f, 0.f, 0.f, 0.f};
        #pragma unroll 4
        for (int j = 0; j < 64; ++j) {
            float h = sH2[rr * 68 + j];
            #pragma unroll
            for (int c = 0; c < 6; ++c)
                acc[c] = fmaf(h, sW3[(ch + c) * 64 + j], acc[c]);
        }
        #pragma unroll
        for (int c = 0; c < 6; ++c)
            out[(base + rr) * NCLS + ch + c] = acc[c] + b3[ch + c];
    }
}

// ---------------------------------------------------------------------------
extern "C" void kernel_launch(void* const* d_in, const int* in_sizes, int n_in,
                              void* d_out, int out_size) {
    const float* x     = (const float*)d_in[0];
    const float* mzi   = (const float*)d_in[1];
    const float* oph   = (const float*)d_in[2];
    const float* betap = (const float*)d_in[3];
    const float* det0  = (const float*)d_in[4];
    const float* W1    = (const float*)d_in[5];
    const float* b1    = (const float*)d_in[6];
    const float* W2    = (const float*)d_in[7];
    const float* b2    = (const float*)d_in[8];
    const float* W3    = (const float*)d_in[9];
    const float* b3    = (const float*)d_in[10];
    float* out = (float*)d_out;

    const int rows = in_sizes[0] / NF;
    const int grid = rows / TILE_R;

    cudaFuncSetAttribute(ficonn_main, cudaFuncAttributeMaxDynamicSharedMemorySize, SMEM_TOTAL);

    trig_kernel<<<(NL * NMZI + 255) / 256, 256>>>(mzi);
    build_unitaries<<<NL, 64>>>(oph);
    prep_mlp<<<64, 256>>>(W1, W2);
    ficonn_main<<<grid, TPB, SMEM_TOTAL>>>(x, betap, det0, b1, b2, W3, b3, out);
}

// round 5
// speedup vs baseline: 3.1090x; 1.2385x over previous
#include <cuda_runtime.h>
#include <math.h>

#define NF    64
#define NL    5
#define NMZI  2016
#define NCLS  12
#define TILE_R 64
#define TPB   256

#define CHALF 0.70710678118654752f
#define GAM   0.05f
#define GAM2  0.0025f

typedef unsigned int u32;
typedef unsigned short u16;

// strides
#define ASTR   136      // A row stride, bf16 elems
#define ASTRW  68       // in 32-bit words
#define BSTRW  68       // layer/W2 B^T row stride in words
#define W1STRW 36       // W1 B^T row stride in words (72 bf16)

// smem layout (bytes)
#define OFF_AH 0                     // 64 x 136 bf16 = 17408
#define OFF_AL 17408
#define OFF_BH 34816                 // B plane hi (34816: 128 x 136 bf16)
#define OFF_BL 69632                 // B plane lo
#define OFF_W3 OFF_BH                // W3 overlay (3072)
#define OFF_H2 (OFF_BH + 4096)       // h2 fp32 64x68 = 17408 (overlay in B region)
#define OFF_PAR 104448               // 64 x float4
#define OFF_B1 105472                // 128 f32
#define OFF_B2 105984                // 64 f32
#define SMEM_TOTAL 106240

// device global staging
__device__ float4 g_trig_unused[1];  // (kept out; trig now in-kernel)
__device__ __align__(16) u16 g_Bu[NL * 2 * 128 * ASTR];   // per layer: hi, lo planes (B^T)
__device__ __align__(16) u16 g_Bw1[2 * 128 * 72];
__device__ __align__(16) u16 g_Bw2[2 * 64 * ASTR];

// ---------------- helpers ----------------
__device__ __forceinline__ u16 f2bf(float f) {
    u16 h; asm("cvt.rn.bf16.f32 %0, %1;" : "=h"(h) : "f"(f)); return h;
}
__device__ __forceinline__ u16 f2bf_hi(float f, float& fh) {
    u16 h; asm("cvt.rn.bf16.f32 %0, %1;" : "=h"(h) : "f"(f));
    fh = __uint_as_float(((u32)h) << 16); return h;
}
__device__ __forceinline__ void mma_bf16(float* d, const u32* a, const u32* b) {
    asm volatile(
        "mma.sync.aligned.m16n8k16.row.col.f32.bf16.bf16.f32 "
        "{%0,%1,%2,%3},{%4,%5,%6,%7},{%8,%9},{%0,%1,%2,%3};"
        : "+f"(d[0]), "+f"(d[1]), "+f"(d[2]), "+f"(d[3])
        : "r"(a[0]), "r"(a[1]), "r"(a[2]), "r"(a[3]), "r"(b[0]), "r"(b[1]));
}

// ---------------------------------------------------------------------------
// Unified unitary builder: trig + serial scan + coalesced write-out.
// 5 blocks x 256 threads; dynamic smem 65536.
//   smem: strig[NMZI] float4 @0 (32256), sU[64*64] float2 @32256 (32768),
//         sco @65024 (256), ssi @65280 (256)
// ---------------------------------------------------------------------------
__global__ void build_unitaries(const float* __restrict__ mzi,
                                const float* __restrict__ ophase) {
    extern __shared__ char sm[];
    float4* strig = (float4*)sm;
    float2* sU    = (float2*)(sm + 32256);
    float*  sco   = (float*)(sm + 65024);
    float*  ssi   = (float*)(sm + 65280);

    const int l = blockIdx.x;
    const int t = threadIdx.x;

    // phase 1: trig (parallel over 256 threads)
    for (int k = t; k < NMZI; k += TPB) {
        float th = mzi[l * (2 * NMZI) + 2 * k];
        float ph = mzi[l * (2 * NMZI) + 2 * k + 1];
        float st, ct, sp, cp;
        sincosf(th, &st, &ct);
        sincosf(ph, &sp, &cp);
        strig[k] = make_float4(ct, st, cp, sp);
    }
    if (t < 64) {
        float s, c; sincosf(ophase[l * NF + t], &s, &c);
        sco[t] = c; ssi[t] = s;
    }
    // identity init
    for (int idx = t; idx < NF * NF; idx += TPB) {
        int r = idx >> 6, c = idx & 63;
        sU[idx] = make_float2(r == c ? 1.f : 0.f, 0.f);
    }
    __syncthreads();

    // phase 2: serial scan, threads 0..63 (column t), prefetched inner loop
    if (t < 64) {
        int k = 0;
        for (int i = 0; i < 63; ++i) {
            float2 ui = sU[i * NF + t];
            float2 uj = sU[(i + 1) * NF + t];
            for (int j = i + 1; j < 64; ++j, ++k) {
                float2 ujn = (j + 1 < 64) ? sU[(j + 1) * NF + t] : make_float2(0.f, 0.f);
                float4 tr = strig[k];
                float epx = tr.z * uj.x - tr.w * uj.y;
                float epy = tr.z * uj.y + tr.w * uj.x;
                float dx = ui.x - epx, dy = ui.y - epy;
                float2 nj;
                nj.x = CHALF * (tr.x * dx - tr.y * dy);
                nj.y = CHALF * (tr.y * dx + tr.x * dy);
                sU[j * NF + t] = nj;
                ui.x = CHALF * (ui.x + epx);
                ui.y = CHALF * (ui.y + epy);
                uj = ujn;
            }
            sU[i * NF + t] = ui;
        }
    }
    __syncthreads();

    // phase 3: write-out, all 256 threads over (c, j) pairs
    u16* hi = g_Bu + l * 2 * 128 * ASTR;
    u16* lo = hi + 128 * ASTR;
    u32* hiw = (u32*)hi;
    u32* low = (u32*)lo;
    for (int idx = t; idx < NF * NF; idx += TPB) {
        int c = idx >> 6, j = idx & 63;
        float co = sco[c], si = ssi[c];
        float2 v = sU[c * NF + j];
        float ur = co * v.x - si * v.y;
        float um = co * v.y + si * v.x;
        float fh;
        u16 urh = f2bf_hi(ur, fh); u16 url = f2bf(ur - fh);
        u16 uih = f2bf_hi(um, fh); u16 uil = f2bf(um - fh);
        if (l == 0) {
            // K=64 layout: row 2c col j = Ur ; row 2c+1 col j = Ui
            hi[(2 * c) * ASTR + j] = urh;     lo[(2 * c) * ASTR + j] = url;
            hi[(2 * c + 1) * ASTR + j] = uih; lo[(2 * c + 1) * ASTR + j] = uil;
        } else {
            // interleaved K=128: row 2c word j = {Ur, -Ui}; row 2c+1 word j = {Ui, Ur}
            u32 nuih = (u32)(u16)(uih ^ 0x8000);
            u32 nuil = (u32)(u16)(uil ^ 0x8000);
            hiw[(2 * c) * ASTRW + j]     = (u32)urh | (nuih << 16);
            low[(2 * c) * ASTRW + j]     = (u32)url | (nuil << 16);
            hiw[(2 * c + 1) * ASTRW + j] = (u32)uih | ((u32)urh << 16);
            low[(2 * c + 1) * ASTRW + j] = (u32)uil | ((u32)url << 16);
        }
    }
}

// ---------------------------------------------------------------------------
__global__ void prep_mlp(const float* __restrict__ W1, const float* __restrict__ W2) {
    int idx = blockIdx.x * blockDim.x + threadIdx.x;
    if (idx < 8192) {
        int m = idx >> 6, j = idx & 63;
        float v = W1[idx];
        float fh; u16 h = f2bf_hi(v, fh); u16 lo = f2bf(v - fh);
        g_Bw1[m * 72 + j] = h;
        g_Bw1[128 * 72 + m * 72 + j] = lo;
    } else if (idx < 16384) {
        int i2 = idx - 8192;
        int n = i2 >> 7, m = i2 & 127;
        float v = W2[i2];
        float fh; u16 h = f2bf_hi(v, fh); u16 lo = f2bf(v - fh);
        g_Bw2[n * ASTR + m] = h;
        g_Bw2[64 * ASTR + n * ASTR + m] = lo;
    }
}

// ---------------------------------------------------------------------------
// Main fused kernel: mma.sync bf16x3, TILE_R=64, 2 CTAs/SM.
// ---------------------------------------------------------------------------
__global__ __launch_bounds__(TPB, 2)
void ficonn_main(const float* __restrict__ x,
                 const float* __restrict__ beta_param,
                 const float* __restrict__ det0,
                 const float* __restrict__ b1,
                 const float* __restrict__ b2,
                 const float* __restrict__ W3, const float* __restrict__ b3,
                 float* __restrict__ out)
{
    extern __shared__ char smem[];
    const int t = threadIdx.x;
    const int wid = t >> 5;
    const int lane = t & 31;
    const int g = lane >> 2;     // groupID
    const int q = lane & 3;      // quad lane
    const long base = (long)blockIdx.x * TILE_R;

    u32* pAH = (u32*)(smem + OFF_AH);
    u32* pAL = (u32*)(smem + OFF_AL);
    float4* sPar = (float4*)(smem + OFF_PAR);
    float*  sB1  = (float*)(smem + OFF_B1);
    float*  sB2  = (float*)(smem + OFF_B2);
    float*  sH2  = (float*)(smem + OFF_H2);

    // warp grid for M=64,N=128: 2(M) x 4(N); warp tile 32x32
    const int m0 = (wid >> 2) * 32;
    const int n0 = (wid & 3) * 32;

    // ---- init: x -> A planes (layer-0 layout, K=64) ----
    {
        const float4* xv = (const float4*)(x + base * NF);
        for (int idx = t; idx < TILE_R * (NF / 4); idx += TPB) {
            int r = idx >> 4, c4 = (idx & 15) * 4;
            float4 v = xv[idx];
            float f0, f1, f2, f3;
            u16 h0 = f2bf_hi(v.x, f0), h1 = f2bf_hi(v.y, f1);
            u16 h2 = f2bf_hi(v.z, f2), h3 = f2bf_hi(v.w, f3);
            int w = r * ASTRW + (c4 >> 1);
            *(uint2*)(pAH + w) = make_uint2((u32)h0 | ((u32)h1 << 16), (u32)h2 | ((u32)h3 << 16));
            *(uint2*)(pAL + w) = make_uint2(
                (u32)f2bf(v.x - f0) | ((u32)f2bf(v.y - f1) << 16),
                (u32)f2bf(v.z - f2) | ((u32)f2bf(v.w - f3) << 16));
        }
        if (t < 128) sB1[t] = b1[t];
        else if (t < 192) sB2[t - 128] = b2[t - 128];
    }

    // ================= photonic layers =================
    for (int l = 0; l < NL; ++l) {
        // stage B planes (69632 B)
        {
            const uint4* gB = (const uint4*)(g_Bu + l * 2 * 128 * ASTR);
            uint4* dB = (uint4*)(smem + OFF_BH);
            #pragma unroll
            for (int i = 0; i < 17; ++i) dB[t + i * TPB] = gB[t + i * TPB];
        }
        if (l < NL - 1 && t < 64) {
            float bp = beta_param[l * NF + t];
            float beta = 1.f / (1.f + expf(-bp));
            float sgam = sqrtf(fmaxf(1.f - beta, 0.f)) * GAM;
            sPar[t] = make_float4(sgam, 0.0008f * beta, det0[l * NF + t], 0.f);
        }
        __syncthreads();

        const u32* pBH = (const u32*)(smem + OFF_BH);
        const u32* pBL = (const u32*)(smem + OFF_BL);

        float acc[2][4][4];
        #pragma unroll
        for (int mt = 0; mt < 2; ++mt)
            #pragma unroll
            for (int nt = 0; nt < 4; ++nt)
                #pragma unroll
                for (int e = 0; e < 4; ++e) acc[mt][nt][e] = 0.f;

        const int kmax = (l == 0) ? 4 : 8;
        for (int kk = 0; kk < kmax; ++kk) {
            u32 ah[2][4], al[2][4], bh[4][2], bl[4][2];
            #pragma unroll
            for (int mt = 0; mt < 2; ++mt) {
                int w = (m0 + mt * 16 + g) * ASTRW + kk * 8 + q;
                ah[mt][0] = pAH[w]; ah[mt][1] = pAH[w + 8 * ASTRW];
                ah[mt][2] = pAH[w + 4]; ah[mt][3] = pAH[w + 8 * ASTRW + 4];
                al[mt][0] = pAL[w]; al[mt][1] = pAL[w + 8 * ASTRW];
                al[mt][2] = pAL[w + 4]; al[mt][3] = pAL[w + 8 * ASTRW + 4];
            }
            #pragma unroll
            for (int nt = 0; nt < 4; ++nt) {
                int w = (n0 + nt * 8 + g) * BSTRW + kk * 8 + q;
                bh[nt][0] = pBH[w]; bh[nt][1] = pBH[w + 4];
                bl[nt][0] = pBL[w]; bl[nt][1] = pBL[w + 4];
            }
            #pragma unroll
            for (int mt = 0; mt < 2; ++mt)
                #pragma unroll
                for (int nt = 0; nt < 4; ++nt) {
                    mma_bf16(acc[mt][nt], ah[mt], bh[nt]);
                    mma_bf16(acc[mt][nt], ah[mt], bl[nt]);
                    mma_bf16(acc[mt][nt], al[mt], bh[nt]);
                }
        }
        __syncthreads();   // all smem reads done

        if (l < NL - 1) {
            // nofu epilogue; write A interleaved (K=128)
            #pragma unroll
            for (int mt = 0; mt < 2; ++mt) {
                #pragma unroll
                for (int nt = 0; nt < 4; ++nt) {
                    int c = (n0 >> 1) + nt * 4 + q;
                    float4 pr = sPar[c];
                    #pragma unroll
                    for (int h = 0; h < 2; ++h) {
                        int row = m0 + mt * 16 + g + h * 8;
                        float fx = acc[mt][nt][2 * h];
                        float fy = acc[mt][nt][2 * h + 1];
                        float pw = fx * fx + fy * fy;
                        float det = fmaf(pr.y, pw, pr.z);
                        float s = pr.x * __fdividef(1.f, fmaf(det, det, GAM2));
                        float ox = s * fmaf(fy, det, fx * GAM);
                        float oy = s * fmaf(-fx, det, fy * GAM);
                        float fa, fb;
                        u16 xh = f2bf_hi(ox, fa), yh = f2bf_hi(oy, fb);
                        int w = row * ASTRW + c;
                        pAH[w] = (u32)xh | ((u32)yh << 16);
                        pAL[w] = (u32)f2bf(ox - fa) | ((u32)f2bf(oy - fb) << 16);
                    }
                }
            }
        } else {
            // |field|^2 -> P in layer-0 layout (K=64)
            u16* hAH = (u16*)(smem + OFF_AH);
            u16* hAL = (u16*)(smem + OFF_AL);
            #pragma unroll
            for (int mt = 0; mt < 2; ++mt) {
                #pragma unroll
                for (int nt = 0; nt < 4; ++nt) {
                    int c = (n0 >> 1) + nt * 4 + q;
                    #pragma unroll
                    for (int h = 0; h < 2; ++h) {
                        int row = m0 + mt * 16 + g + h * 8;
                        float fx = acc[mt][nt][2 * h];
                        float fy = acc[mt][nt][2 * h + 1];
                        float pw = fx * fx + fy * fy;
                        float fa; u16 ph = f2bf_hi(pw, fa);
                        hAH[row * ASTR + c] = ph;
                        hAL[row * ASTR + c] = f2bf(pw - fa);
                    }
                }
            }
        }
        __syncthreads();
    }

    // ================= GEMM1: h1 = relu(P @ W1^T + b1), M=64 N=128 K=64 =========
    {
        const uint4* gB = (const uint4*)g_Bw1;
        uint4* dB = (uint4*)(smem + OFF_BH);
        for (int i = t; i < 36864 / 16; i += TPB) dB[i] = gB[i];
    }
    __syncthreads();
    {
        const u32* pBH = (const u32*)(smem + OFF_BH);
        const u32* pBL = (const u32*)(smem + OFF_BH + 18432);

        float acc[2][4][4];
        #pragma unroll
        for (int mt = 0; mt < 2; ++mt)
            #pragma unroll
            for (int nt = 0; nt < 4; ++nt)
                #pragma unroll
                for (int e = 0; e < 4; ++e) acc[mt][nt][e] = 0.f;

        for (int kk = 0; kk < 4; ++kk) {
            u32 ah[2][4], al[2][4], bh[4][2], bl[4][2];
            #pragma unroll
            for (int mt = 0; mt < 2; ++mt) {
                int w = (m0 + mt * 16 + g) * ASTRW + kk * 8 + q;
                ah[mt][0] = pAH[w]; ah[mt][1] = pAH[w + 8 * ASTRW];
                ah[mt][2] = pAH[w + 4]; ah[mt][3] = pAH[w + 8 * ASTRW + 4];
                al[mt][0] = pAL[w]; al[mt][1] = pAL[w + 8 * ASTRW];
                al[mt][2] = pAL[w + 4]; al[mt][3] = pAL[w + 8 * ASTRW + 4];
            }
            #pragma unroll
            for (int nt = 0; nt < 4; ++nt) {
                int w = (n0 + nt * 8 + g) * W1STRW + kk * 8 + q;
                bh[nt][0] = pBH[w]; bh[nt][1] = pBH[w + 4];
                bl[nt][0] = pBL[w]; bl[nt][1] = pBL[w + 4];
            }
            #pragma unroll
            for (int mt = 0; mt < 2; ++mt)
                #pragma unroll
                for (int nt = 0; nt < 4; ++nt) {
                    mma_bf16(acc[mt][nt], ah[mt], bh[nt]);
                    mma_bf16(acc[mt][nt], ah[mt], bl[nt]);
                    mma_bf16(acc[mt][nt], al[mt], bh[nt]);
                }
        }
        __syncthreads();

        // stage W2
        {
            const uint4* gB = (const uint4*)g_Bw2;
            uint4* dB = (uint4*)(smem + OFF_BH);
            for (int i = t; i < 34816 / 16; i += TPB) dB[i] = gB[i];
        }
        // epilogue: relu+bias -> h1 into A planes (K=128 layout)
        #pragma unroll
        for (int mt = 0; mt < 2; ++mt) {
            #pragma unroll
            for (int nt = 0; nt < 4; ++nt) {
                int col = n0 + nt * 8 + q * 2;
                float bb0 = sB1[col], bb1 = sB1[col + 1];
                #pragma unroll
                for (int h = 0; h < 2; ++h) {
                    int row = m0 + mt * 16 + g + h * 8;
                    float v0 = fmaxf(acc[mt][nt][2 * h] + bb0, 0.f);
                    float v1 = fmaxf(acc[mt][nt][2 * h + 1] + bb1, 0.f);
                    float fa, fb;
                    u16 h0 = f2bf_hi(v0, fa), h1v = f2bf_hi(v1, fb);
                    int w = row * ASTRW + (col >> 1);
                    pAH[w] = (u32)h0 | ((u32)h1v << 16);
                    pAL[w] = (u32)f2bf(v0 - fa) | ((u32)f2bf(v1 - fb) << 16);
                }
            }
        }
    }
    __syncthreads();

    // ================= GEMM2: h2 = relu(h1 @ W2^T + b2), M=64 N=64 K=128 ========
    // warps 4(M) x 2(N); warp tile 16 x 32
    {
        const u32* pBH = (const u32*)(smem + OFF_BH);
        const u32* pBL = (const u32*)(smem + OFF_BH + 17408);
        const int mb = (wid >> 1) * 16;
        const int nb = (wid & 1) * 32;

        float acc[4][4];
        #pragma unroll
        for (int nt = 0; nt < 4; ++nt)
            #pragma unroll
            for (int e = 0; e < 4; ++e) acc[nt][e] = 0.f;

        for (int kk = 0; kk < 8; ++kk) {
            u32 ah[4], al[4], bh[4][2], bl[4][2];
            {
                int w = (mb + g) * ASTRW + kk * 8 + q;
                ah[0] = pAH[w]; ah[1] = pAH[w + 8 * ASTRW];
                ah[2] = pAH[w + 4]; ah[3] = pAH[w + 8 * ASTRW + 4];
                al[0] = pAL[w]; al[1] = pAL[w + 8 * ASTRW];
                al[2] = pAL[w + 4]; al[3] = pAL[w + 8 * ASTRW + 4];
            }
            #pragma unroll
            for (int nt = 0; nt < 4; ++nt) {
                int w = (nb + nt * 8 + g) * BSTRW + kk * 8 + q;
                bh[nt][0] = pBH[w]; bh[nt][1] = pBH[w + 4];
                bl[nt][0] = pBL[w]; bl[nt][1] = pBL[w + 4];
            }
            #pragma unroll
            for (int nt = 0; nt < 4; ++nt) {
                mma_bf16(acc[nt], ah, bh[nt]);
                mma_bf16(acc[nt], ah, bl[nt]);
                mma_bf16(acc[nt], al, bh[nt]);
            }
        }
        __syncthreads();   // h1/W2 reads done

        // stage W3 (B region head); epilogue -> sH2 (overlay in B region)
        {
            float* sW3 = (float*)(smem + OFF_W3);
            for (int i = t; i < NCLS * 64; i += TPB) sW3[i] = W3[i];
        }
        #pragma unroll
        for (int nt = 0; nt < 4; ++nt) {
            int col = nb + nt * 8 + q * 2;
            float bb0 = sB2[col], bb1 = sB2[col + 1];
            #pragma unroll
            for (int h = 0; h < 2; ++h) {
                int row = mb + g + h * 8;
                sH2[row * 68 + col]     = fmaxf(acc[nt][2 * h] + bb0, 0.f);
                sH2[row * 68 + col + 1] = fmaxf(acc[nt][2 * h + 1] + bb1, 0.f);
            }
        }
    }
    __syncthreads();

    // ================= GEMM3 (scalar): out = h2 @ W3^T + b3 =================
    {
        const float* sW3 = (const float*)(smem + OFF_W3);
        const int rr = t >> 2;            // 0..63
        const int ch = (t & 3) * 3;       // 0,3,6,9
        float acc[3] = {0.f, 0.f, 0.f};
        #pragma unroll 4
        for (int j = 0; j < 64; ++j) {
            float h = sH2[rr * 68 + j];
            #pragma unroll
            for (int c = 0; c < 3; ++c)
                acc[c] = fmaf(h, sW3[(ch + c) * 64 + j], acc[c]);
        }
        #pragma unroll
        for (int c = 0; c < 3; ++c)
            out[(base + rr) * NCLS + ch + c] = acc[c] + b3[ch + c];
    }
}

// ---------------------------------------------------------------------------
extern "C" void kernel_launch(void* const* d_in, const int* in_sizes, int n_in,
                              void* d_out, int out_size) {
    const float* x     = (const float*)d_in[0];
    const float* mzi   = (const float*)d_in[1];
    const float* oph   = (const float*)d_in[2];
    const float* betap = (const float*)d_in[3];
    const float* det0  = (const float*)d_in[4];
    const float* W1    = (const float*)d_in[5];
    const float* b1    = (const float*)d_in[6];
    const float* W2    = (const float*)d_in[7];
    const float* b2    = (const float*)d_in[8];
    const float* W3    = (const float*)d_in[9];
    const float* b3    = (const float*)d_in[10];
    float* out = (float*)d_out;

    const int rows = in_sizes[0] / NF;
    const int grid = rows / TILE_R;

    cudaFuncSetAttribute(build_unitaries, cudaFuncAttributeMaxDynamicSharedMemorySize, 65536);
    cudaFuncSetAttribute(ficonn_main, cudaFuncAttributeMaxDynamicSharedMemorySize, SMEM_TOTAL);

    build_unitaries<<<NL, TPB, 65536>>>(mzi, oph);
    prep_mlp<<<64, 256>>>(W1, W2);
    ficonn_main<<<grid, TPB, SMEM_TOTAL>>>(x, betap, det0, b1, b2, W3, b3, out);
}

// round 6
// speedup vs baseline: 3.2465x; 1.0442x over previous
#include <cuda_runtime.h>
#include <math.h>

#define NF    64
#define NL    5
#define NMZI  2016
#define NCLS  12
#define TILE_R 64
#define TPB   256

#define CHALF 0.70710678118654752f
#define GAM   0.05f
#define GAM2  0.0025f

typedef unsigned int u32;
typedef unsigned short u16;

// strides
#define ASTR   136
#define ASTRW  68
#define BSTRW  68
#define W1STRW 36

// smem layout (bytes)
#define OFF_AH 0
#define OFF_AL 17408
#define OFF_BH 34816
#define OFF_BL 69632
#define OFF_W3 OFF_BH
#define OFF_H2 (OFF_BH + 4096)
#define OFF_PAR 104448               // 4 layers x 64 x float4 = 4096
#define OFF_B1 108544
#define OFF_B2 109056
#define SMEM_TOTAL 109312

// device global staging
__device__ __align__(16) u16 g_Bu[NL * 2 * 128 * ASTR];
__device__ __align__(16) u16 g_Bw1[2 * 128 * 72];
__device__ __align__(16) u16 g_Bw2[2 * 64 * ASTR];

// ---------------- helpers ----------------
__device__ __forceinline__ u16 f2bf(float f) {
    u16 h; asm("cvt.rn.bf16.f32 %0, %1;" : "=h"(h) : "f"(f)); return h;
}
__device__ __forceinline__ u16 f2bf_hi(float f, float& fh) {
    u16 h; asm("cvt.rn.bf16.f32 %0, %1;" : "=h"(h) : "f"(f));
    fh = __uint_as_float(((u32)h) << 16); return h;
}
__device__ __forceinline__ void mma_bf16(float* d, const u32* a, const u32* b) {
    asm volatile(
        "mma.sync.aligned.m16n8k16.row.col.f32.bf16.bf16.f32 "
        "{%0,%1,%2,%3},{%4,%5,%6,%7},{%8,%9},{%0,%1,%2,%3};"
        : "+f"(d[0]), "+f"(d[1]), "+f"(d[2]), "+f"(d[3])
        : "r"(a[0]), "r"(a[1]), "r"(a[2]), "r"(a[3]), "r"(b[0]), "r"(b[1]));
}
__device__ __forceinline__ void ldsm4(u32 addr, u32* r) {
    asm volatile("ldmatrix.sync.aligned.m8n8.x4.shared.b16 {%0,%1,%2,%3}, [%4];"
        : "=r"(r[0]), "=r"(r[1]), "=r"(r[2]), "=r"(r[3]) : "r"(addr));
}
__device__ __forceinline__ u32 smem_u32(const void* p) {
    u32 a;
    asm("{ .reg .u64 t; cvta.to.shared.u64 t, %1; cvt.u32.u64 %0, t; }" : "=r"(a) : "l"(p));
    return a;
}

// kk-loop MMA block: A 32 rows (2 mt), B 32 cols (4 nt), 3-term bf16 split
template <int KMAX>
__device__ __forceinline__ void mma_block(float acc[2][4][4],
                                          const u32 aA[2][2],   // [plane][mt]
                                          const u32 bB[2][2]) { // [plane][ntp]
#pragma unroll
    for (int kk = 0; kk < KMAX; ++kk) {
        u32 ah[2][4], al[2][4], b_h[2][4], b_l[2][4];
        ldsm4(aA[0][0] + kk * 32, ah[0]);
        ldsm4(aA[0][1] + kk * 32, ah[1]);
        ldsm4(aA[1][0] + kk * 32, al[0]);
        ldsm4(aA[1][1] + kk * 32, al[1]);
        ldsm4(bB[0][0] + kk * 32, b_h[0]);
        ldsm4(bB[0][1] + kk * 32, b_h[1]);
        ldsm4(bB[1][0] + kk * 32, b_l[0]);
        ldsm4(bB[1][1] + kk * 32, b_l[1]);
#pragma unroll
        for (int mt = 0; mt < 2; ++mt)
#pragma unroll
            for (int nt = 0; nt < 4; ++nt) {
                const u32* bh = &b_h[nt >> 1][(nt & 1) * 2];
                const u32* bl = &b_l[nt >> 1][(nt & 1) * 2];
                mma_bf16(acc[mt][nt], ah[mt], bh);
                mma_bf16(acc[mt][nt], ah[mt], bl);
                mma_bf16(acc[mt][nt], al[mt], bh);
            }
    }
}

// ---------------------------------------------------------------------------
// Unitary builder: trig + serial scan (depth-4 prefetch) + write-out.
// smem: strig @0 (32256), sU 68x64 float2 @32256 (34816), sco @67072, ssi @67328
// ---------------------------------------------------------------------------
__global__ void build_unitaries(const float* __restrict__ mzi,
                                const float* __restrict__ ophase) {
    extern __shared__ char sm[];
    float4* strig = (float4*)sm;
    float2* sU    = (float2*)(sm + 32256);
    float*  sco   = (float*)(sm + 67072);
    float*  ssi   = (float*)(sm + 67328);

    const int l = blockIdx.x;
    const int t = threadIdx.x;

    for (int k = t; k < NMZI; k += TPB) {
        float th = mzi[l * (2 * NMZI) + 2 * k];
        float ph = mzi[l * (2 * NMZI) + 2 * k + 1];
        float st, ct, sp, cp;
        sincosf(th, &st, &ct);
        sincosf(ph, &sp, &cp);
        strig[k] = make_float4(ct, st, cp, sp);
    }
    if (t < 64) {
        float s, c; sincosf(ophase[l * NF + t], &s, &c);
        sco[t] = c; ssi[t] = s;
    }
    for (int idx = t; idx < 68 * NF; idx += TPB) {
        int r = idx >> 6, c = idx & 63;
        sU[idx] = make_float2((r == c && r < 64) ? 1.f : 0.f, 0.f);
    }
    __syncthreads();

    if (t < 64) {
        int k = 0;
        for (int i = 0; i < 63; ++i) {
            float2 ui = sU[i * NF + t];
            float2 b0 = sU[(i + 1) * NF + t];
            float2 b1 = sU[(i + 2) * NF + t];
            float2 b2 = sU[(i + 3) * NF + t];
            float2 b3 = sU[(i + 4) * NF + t];
            const int cnt = 63 - i;
            for (int d = 0; d < cnt; d += 4) {
                #define STEP(BUF, OFFS)                                            \
                {                                                                  \
                    int j = i + 1 + d + (OFFS);                                    \
                    float4 tr = strig[k]; ++k;                                     \
                    float epx = tr.z * BUF.x - tr.w * BUF.y;                       \
                    float epy = tr.z * BUF.y + tr.w * BUF.x;                       \
                    float dx = ui.x - epx, dy = ui.y - epy;                        \
                    float2 nj;                                                     \
                    nj.x = CHALF * (tr.x * dx - tr.y * dy);                        \
                    nj.y = CHALF * (tr.y * dx + tr.x * dy);                        \
                    sU[j * NF + t] = nj;                                           \
                    ui.x = CHALF * (ui.x + epx);                                   \
                    ui.y = CHALF * (ui.y + epy);                                   \
                    BUF = sU[(j + 4) * NF + t];                                    \
                }
                STEP(b0, 0)
                if (d + 1 < cnt) STEP(b1, 1)
                if (d + 2 < cnt) STEP(b2, 2)
                if (d + 3 < cnt) STEP(b3, 3)
                #undef STEP
            }
            sU[i * NF + t] = ui;
        }
    }
    __syncthreads();

    u16* hi = g_Bu + l * 2 * 128 * ASTR;
    u16* lo = hi + 128 * ASTR;
    u32* hiw = (u32*)hi;
    u32* low = (u32*)lo;
    for (int idx = t; idx < NF * NF; idx += TPB) {
        int c = idx >> 6, j = idx & 63;
        float co = sco[c], si = ssi[c];
        float2 v = sU[c * NF + j];
        float ur = co * v.x - si * v.y;
        float um = co * v.y + si * v.x;
        float fh;
        u16 urh = f2bf_hi(ur, fh); u16 url = f2bf(ur - fh);
        u16 uih = f2bf_hi(um, fh); u16 uil = f2bf(um - fh);
        if (l == 0) {
            hi[(2 * c) * ASTR + j] = urh;     lo[(2 * c) * ASTR + j] = url;
            hi[(2 * c + 1) * ASTR + j] = uih; lo[(2 * c + 1) * ASTR + j] = uil;
        } else {
            u32 nuih = (u32)(u16)(uih ^ 0x8000);
            u32 nuil = (u32)(u16)(uil ^ 0x8000);
            hiw[(2 * c) * ASTRW + j]     = (u32)urh | (nuih << 16);
            low[(2 * c) * ASTRW + j]     = (u32)url | (nuil << 16);
            hiw[(2 * c + 1) * ASTRW + j] = (u32)uih | ((u32)urh << 16);
            low[(2 * c + 1) * ASTRW + j] = (u32)uil | ((u32)url << 16);
        }
    }
}

// ---------------------------------------------------------------------------
__global__ void prep_mlp(const float* __restrict__ W1, const float* __restrict__ W2) {
    int idx = blockIdx.x * blockDim.x + threadIdx.x;
    if (idx < 8192) {
        int m = idx >> 6, j = idx & 63;
        float v = W1[idx];
        float fh; u16 h = f2bf_hi(v, fh); u16 lo = f2bf(v - fh);
        g_Bw1[m * 72 + j] = h;
        g_Bw1[128 * 72 + m * 72 + j] = lo;
    } else if (idx < 16384) {
        int i2 = idx - 8192;
        int n = i2 >> 7, m = i2 & 127;
        float v = W2[i2];
        float fh; u16 h = f2bf_hi(v, fh); u16 lo = f2bf(v - fh);
        g_Bw2[n * ASTR + m] = h;
        g_Bw2[64 * ASTR + n * ASTR + m] = lo;
    }
}

// ---------------------------------------------------------------------------
// Main fused kernel.
// ---------------------------------------------------------------------------
__global__ __launch_bounds__(TPB, 2)
void ficonn_main(const float* __restrict__ x,
                 const float* __restrict__ beta_param,
                 const float* __restrict__ det0,
                 const float* __restrict__ b1,
                 const float* __restrict__ b2,
                 const float* __restrict__ W3, const float* __restrict__ b3,
                 float* __restrict__ out)
{
    extern __shared__ char smem[];
    const u32 sb = smem_u32(smem);
    const int t = threadIdx.x;
    const int wid = t >> 5;
    const int lane = t & 31;
    const int g = lane >> 2;
    const int q = lane & 3;
    const long base = (long)blockIdx.x * TILE_R;

    u32* pAH = (u32*)(smem + OFF_AH);
    u32* pAL = (u32*)(smem + OFF_AL);
    float4* sPar = (float4*)(smem + OFF_PAR);   // [l][c]
    float*  sB1  = (float*)(smem + OFF_B1);
    float*  sB2  = (float*)(smem + OFF_B2);
    float*  sH2  = (float*)(smem + OFF_H2);

    const int m0 = (wid >> 2) * 32;
    const int n0 = (wid & 3) * 32;

    // ldmatrix lane geometry
    const int mi   = lane >> 3;          // matrix index 0..3
    const int arow = (mi & 1) * 8 + (lane & 7);
    const int aseg = (mi >> 1) * 4;      // word offset within row
    const int brow8 = (lane & 7);
    const int bnt   = (lane >> 4);       // ntp sub-select
    const int bseg  = ((lane >> 3) & 1) * 4;

    // A fragment addresses [plane][mt]
    u32 aA[2][2];
#pragma unroll
    for (int p = 0; p < 2; ++p)
#pragma unroll
        for (int mt = 0; mt < 2; ++mt)
            aA[p][mt] = sb + (p ? OFF_AL : OFF_AH)
                      + 4 * ((m0 + mt * 16 + arow) * ASTRW + aseg);
    // B fragment addresses for layer GEMMs [plane][ntp]
    u32 bB[2][2];
#pragma unroll
    for (int p = 0; p < 2; ++p)
#pragma unroll
        for (int ntp = 0; ntp < 2; ++ntp)
            bB[p][ntp] = sb + (p ? OFF_BL : OFF_BH)
                       + 4 * ((n0 + (ntp * 2 + bnt) * 8 + brow8) * BSTRW + bseg);
    // W1 B addresses
    u32 bW1[2][2];
#pragma unroll
    for (int p = 0; p < 2; ++p)
#pragma unroll
        for (int ntp = 0; ntp < 2; ++ntp)
            bW1[p][ntp] = sb + OFF_BH + p * 18432
                        + 4 * ((n0 + (ntp * 2 + bnt) * 8 + brow8) * W1STRW + bseg);

    // ---- init: x -> A planes (layer-0 layout, K=64) ----
    {
        const float4* xv = (const float4*)(x + base * NF);
        for (int idx = t; idx < TILE_R * (NF / 4); idx += TPB) {
            int r = idx >> 4, c4 = (idx & 15) * 4;
            float4 v = xv[idx];
            float f0, f1, f2, f3;
            u16 h0 = f2bf_hi(v.x, f0), h1 = f2bf_hi(v.y, f1);
            u16 h2 = f2bf_hi(v.z, f2), h3 = f2bf_hi(v.w, f3);
            int w = r * ASTRW + (c4 >> 1);
            *(uint2*)(pAH + w) = make_uint2((u32)h0 | ((u32)h1 << 16), (u32)h2 | ((u32)h3 << 16));
            *(uint2*)(pAL + w) = make_uint2(
                (u32)f2bf(v.x - f0) | ((u32)f2bf(v.y - f1) << 16),
                (u32)f2bf(v.z - f2) | ((u32)f2bf(v.w - f3) << 16));
        }
        // stage B(0)
        const uint4* gB = (const uint4*)g_Bu;
        uint4* dB = (uint4*)(smem + OFF_BH);
#pragma unroll
        for (int i = 0; i < 17; ++i) dB[t + i * TPB] = gB[t + i * TPB];
        // all nofu params (4 layers x 64)
        {
            int l = t >> 6, c = t & 63;
            if (l < NL - 1) {
                float bp = beta_param[l * NF + c];
                float beta = 1.f / (1.f + expf(-bp));
                float sgam = sqrtf(fmaxf(1.f - beta, 0.f)) * GAM;
                sPar[t] = make_float4(sgam, 0.0008f * beta, det0[l * NF + c], 0.f);
            }
        }
        if (t < 128) sB1[t] = b1[t];
        else if (t < 192) sB2[t - 128] = b2[t - 128];
    }

    // ================= photonic layers =================
    for (int l = 0; l < NL; ++l) {
        __syncthreads();   // A + B(l) ready

        float acc[2][4][4];
#pragma unroll
        for (int mt = 0; mt < 2; ++mt)
#pragma unroll
            for (int nt = 0; nt < 4; ++nt)
#pragma unroll
                for (int e = 0; e < 4; ++e) acc[mt][nt][e] = 0.f;

        if (l == 0) mma_block<4>(acc, aA, bB);
        else        mma_block<8>(acc, aA, bB);

        __syncthreads();   // B reads done

        // stage next B (or W1) — overlaps with epilogue math below
        if (l < NL - 1) {
            const uint4* gB = (const uint4*)(g_Bu + (l + 1) * 2 * 128 * ASTR);
            uint4* dB = (uint4*)(smem + OFF_BH);
#pragma unroll
            for (int i = 0; i < 17; ++i) dB[t + i * TPB] = gB[t + i * TPB];
        } else {
            const uint4* gB = (const uint4*)g_Bw1;
            uint4* dB = (uint4*)(smem + OFF_BH);
            for (int i = t; i < 36864 / 16; i += TPB) dB[i] = gB[i];
        }

        if (l < NL - 1) {
#pragma unroll
            for (int mt = 0; mt < 2; ++mt) {
#pragma unroll
                for (int nt = 0; nt < 4; ++nt) {
                    int c = (n0 >> 1) + nt * 4 + q;
                    float4 pr = sPar[l * 64 + c];
#pragma unroll
                    for (int h = 0; h < 2; ++h) {
                        int row = m0 + mt * 16 + g + h * 8;
                        float fx = acc[mt][nt][2 * h];
                        float fy = acc[mt][nt][2 * h + 1];
                        float pw = fx * fx + fy * fy;
                        float det = fmaf(pr.y, pw, pr.z);
                        float s = pr.x * __fdividef(1.f, fmaf(det, det, GAM2));
                        float ox = s * fmaf(fy, det, fx * GAM);
                        float oy = s * fmaf(-fx, det, fy * GAM);
                        float fa, fb;
                        u16 xh = f2bf_hi(ox, fa), yh = f2bf_hi(oy, fb);
                        int w = row * ASTRW + c;
                        pAH[w] = (u32)xh | ((u32)yh << 16);
                        pAL[w] = (u32)f2bf(ox - fa) | ((u32)f2bf(oy - fb) << 16);
                    }
                }
            }
        } else {
            u16* hAH = (u16*)(smem + OFF_AH);
            u16* hAL = (u16*)(smem + OFF_AL);
#pragma unroll
            for (int mt = 0; mt < 2; ++mt) {
#pragma unroll
                for (int nt = 0; nt < 4; ++nt) {
                    int c = (n0 >> 1) + nt * 4 + q;
#pragma unroll
                    for (int h = 0; h < 2; ++h) {
                        int row = m0 + mt * 16 + g + h * 8;
                        float fx = acc[mt][nt][2 * h];
                        float fy = acc[mt][nt][2 * h + 1];
                        float pw = fx * fx + fy * fy;
                        float fa; u16 ph = f2bf_hi(pw, fa);
                        hAH[row * ASTR + c] = ph;
                        hAL[row * ASTR + c] = f2bf(pw - fa);
                    }
                }
            }
        }
    }
    __syncthreads();   // P + W1 ready

    // ================= GEMM1: M=64 N=128 K=64 =================
    {
        float acc[2][4][4];
#pragma unroll
        for (int mt = 0; mt < 2; ++mt)
#pragma unroll
            for (int nt = 0; nt < 4; ++nt)
#pragma unroll
                for (int e = 0; e < 4; ++e) acc[mt][nt][e] = 0.f;

        mma_block<4>(acc, aA, bW1);
        __syncthreads();

        // stage W2 (overlaps epilogue)
        {
            const uint4* gB = (const uint4*)g_Bw2;
            uint4* dB = (uint4*)(smem + OFF_BH);
            for (int i = t; i < 34816 / 16; i += TPB) dB[i] = gB[i];
        }
#pragma unroll
        for (int mt = 0; mt < 2; ++mt) {
#pragma unroll
            for (int nt = 0; nt < 4; ++nt) {
                int col = n0 + nt * 8 + q * 2;
                float bb0 = sB1[col], bb1 = sB1[col + 1];
#pragma unroll
                for (int h = 0; h < 2; ++h) {
                    int row = m0 + mt * 16 + g + h * 8;
                    float v0 = fmaxf(acc[mt][nt][2 * h] + bb0, 0.f);
                    float v1 = fmaxf(acc[mt][nt][2 * h + 1] + bb1, 0.f);
                    float fa, fb;
                    u16 h0 = f2bf_hi(v0, fa), h1v = f2bf_hi(v1, fb);
                    int w = row * ASTRW + (col >> 1);
                    pAH[w] = (u32)h0 | ((u32)h1v << 16);
                    pAL[w] = (u32)f2bf(v0 - fa) | ((u32)f2bf(v1 - fb) << 16);
                }
            }
        }
    }
    __syncthreads();

    // ================= GEMM2: M=64 N=64 K=128 =================
    {
        const int mb = (wid >> 1) * 16;
        const int nb = (wid & 1) * 32;

        u32 aA2[2];
#pragma unroll
        for (int p = 0; p < 2; ++p)
            aA2[p] = sb + (p ? OFF_AL : OFF_AH) + 4 * ((mb + arow) * ASTRW + aseg);
        u32 bB2[2][2];
#pragma unroll
        for (int p = 0; p < 2; ++p)
#pragma unroll
            for (int ntp = 0; ntp < 2; ++ntp)
                bB2[p][ntp] = sb + OFF_BH + p * 17408
                            + 4 * ((nb + (ntp * 2 + bnt) * 8 + brow8) * BSTRW + bseg);

        float acc[4][4];
#pragma unroll
        for (int nt = 0; nt < 4; ++nt)
#pragma unroll
            for (int e = 0; e < 4; ++e) acc[nt][e] = 0.f;

#pragma unroll
        for (int kk = 0; kk < 8; ++kk) {
            u32 ah[4], al[4], b_h[2][4], b_l[2][4];
            ldsm4(aA2[0] + kk * 32, ah);
            ldsm4(aA2[1] + kk * 32, al);
            ldsm4(bB2[0][0] + kk * 32, b_h[0]);
            ldsm4(bB2[0][1] + kk * 32, b_h[1]);
            ldsm4(bB2[1][0] + kk * 32, b_l[0]);
            ldsm4(bB2[1][1] + kk * 32, b_l[1]);
#pragma unroll
            for (int nt = 0; nt < 4; ++nt) {
                const u32* bh = &b_h[nt >> 1][(nt & 1) * 2];
                const u32* bl = &b_l[nt >> 1][(nt & 1) * 2];
                mma_bf16(acc[nt], ah, bh);
                mma_bf16(acc[nt], ah, bl);
                mma_bf16(acc[nt], al, bh);
            }
        }
        __syncthreads();

        // stage W3; epilogue -> sH2
        {
            float* sW3 = (float*)(smem + OFF_W3);
            for (int i = t; i < NCLS * 64; i += TPB) sW3[i] = W3[i];
        }
#pragma unroll
        for (int nt = 0; nt < 4; ++nt) {
            int col = nb + nt * 8 + q * 2;
            float bb0 = sB2[col], bb1 = sB2[col + 1];
#pragma unroll
            for (int h = 0; h < 2; ++h) {
                int row = mb + g + h * 8;
                sH2[row * 68 + col]     = fmaxf(acc[nt][2 * h] + bb0, 0.f);
                sH2[row * 68 + col + 1] = fmaxf(acc[nt][2 * h + 1] + bb1, 0.f);
            }
        }
    }
    __syncthreads();

    // ================= GEMM3 (scalar) =================
    {
        const float* sW3 = (const float*)(smem + OFF_W3);
        const int rr = t >> 2;
        const int ch = (t & 3) * 3;
        float acc[3] = {0.f, 0.f, 0.f};
#pragma unroll 4
        for (int j = 0; j < 64; ++j) {
            float h = sH2[rr * 68 + j];
#pragma unroll
            for (int c = 0; c < 3; ++c)
                acc[c] = fmaf(h, sW3[(ch + c) * 64 + j], acc[c]);
        }
#pragma unroll
        for (int c = 0; c < 3; ++c)
            out[(base + rr) * NCLS + ch + c] = acc[c] + b3[ch + c];
    }
}

// ---------------------------------------------------------------------------
extern "C" void kernel_launch(void* const* d_in, const int* in_sizes, int n_in,
                              void* d_out, int out_size) {
    const float* x     = (const float*)d_in[0];
    const float* mzi   = (const float*)d_in[1];
    const float* oph   = (const float*)d_in[2];
    const float* betap = (const float*)d_in[3];
    const float* det0  = (const float*)d_in[4];
    const float* W1    = (const float*)d_in[5];
    const float* b1    = (const float*)d_in[6];
    const float* W2    = (const float*)d_in[7];
    const float* b2    = (const float*)d_in[8];
    const float* W3    = (const float*)d_in[9];
    const float* b3    = (const float*)d_in[10];
    float* out = (float*)d_out;

    const int rows = in_sizes[0] / NF;
    const int grid = rows / TILE_R;

    cudaFuncSetAttribute(build_unitaries, cudaFuncAttributeMaxDynamicSharedMemorySize, 67584);
    cudaFuncSetAttribute(ficonn_main, cudaFuncAttributeMaxDynamicSharedMemorySize, SMEM_TOTAL);

    build_unitaries<<<NL, TPB, 67584>>>(mzi, oph);
    prep_mlp<<<64, 256>>>(W1, W2);
    ficonn_main<<<grid, TPB, SMEM_TOTAL>>>(x, betap, det0, b1, b2, W3, b3, out);
}

// round 7
// speedup vs baseline: 3.7278x; 1.1483x over previous
#include <cuda_runtime.h>
#include <math.h>

#define NF    64
#define NL    5
#define NMZI  2016
#define NCLS  12
#define TILE_R 64
#define TPB   256

#define CHALF 0.70710678118654752f
#define GAM   0.05f
#define GAM2  0.0025f

typedef unsigned int u32;
typedef unsigned short u16;

// strides
#define ASTR   136
#define ASTRW  68
#define BSTRW  68
#define W1STRW 36

// smem layout (bytes)
#define OFF_AH 0
#define OFF_AL 17408
#define OFF_BH 34816
#define OFF_BL 69632
#define OFF_W3 OFF_BH
#define OFF_H2 (OFF_BH + 4096)
#define OFF_PAR 104448               // 4 layers x 64 x float4 = 4096
#define OFF_B1 108544
#define OFF_B2 109056
#define SMEM_TOTAL 109312

// device global staging
__device__ __align__(16) u16 g_Bu[NL * 2 * 128 * ASTR];
__device__ __align__(16) u16 g_Bw1[2 * 128 * 72];
__device__ __align__(16) u16 g_Bw2[2 * 64 * ASTR];

// ---------------- helpers ----------------
__device__ __forceinline__ u16 f2bf(float f) {
    u16 h; asm("cvt.rn.bf16.f32 %0, %1;" : "=h"(h) : "f"(f)); return h;
}
__device__ __forceinline__ u16 f2bf_hi(float f, float& fh) {
    u16 h; asm("cvt.rn.bf16.f32 %0, %1;" : "=h"(h) : "f"(f));
    fh = __uint_as_float(((u32)h) << 16); return h;
}
// packed: low half <- lo, high half <- hi
__device__ __forceinline__ u32 packbf(float lo, float hi) {
    u32 r; asm("cvt.rn.bf16x2.f32 %0, %1, %2;" : "=r"(r) : "f"(hi), "f"(lo)); return r;
}
__device__ __forceinline__ void mma_bf16(float* d, const u32* a, const u32* b) {
    asm volatile(
        "mma.sync.aligned.m16n8k16.row.col.f32.bf16.bf16.f32 "
        "{%0,%1,%2,%3},{%4,%5,%6,%7},{%8,%9},{%0,%1,%2,%3};"
        : "+f"(d[0]), "+f"(d[1]), "+f"(d[2]), "+f"(d[3])
        : "r"(a[0]), "r"(a[1]), "r"(a[2]), "r"(a[3]), "r"(b[0]), "r"(b[1]));
}
__device__ __forceinline__ void ldsm4(u32 addr, u32* r) {
    asm volatile("ldmatrix.sync.aligned.m8n8.x4.shared.b16 {%0,%1,%2,%3}, [%4];"
        : "=r"(r[0]), "=r"(r[1]), "=r"(r[2]), "=r"(r[3]) : "r"(addr));
}
__device__ __forceinline__ u32 smem_u32(const void* p) {
    u32 a;
    asm("{ .reg .u64 t; cvta.to.shared.u64 t, %1; cvt.u32.u64 %0, t; }" : "=r"(a) : "l"(p));
    return a;
}
__device__ __forceinline__ void cp16(u32 dst, const void* src) {
    asm volatile("cp.async.ca.shared.global [%0], [%1], 16;" :: "r"(dst), "l"(src));
}
__device__ __forceinline__ void cp_commit() {
    asm volatile("cp.async.commit_group;" ::: "memory");
}
__device__ __forceinline__ void cp_wait_all() {
    asm volatile("cp.async.wait_group 0;" ::: "memory");
}

// kk-loop MMA block: A 32 rows (2 mt), B 32 cols (4 nt), 3-term bf16 split
template <int KMAX>
__device__ __forceinline__ void mma_block(float acc[2][4][4],
                                          const u32 aA[2][2],
                                          const u32 bB[2][2]) {
#pragma unroll
    for (int kk = 0; kk < KMAX; ++kk) {
        u32 ah[2][4], al[2][4], b_h[2][4], b_l[2][4];
        ldsm4(aA[0][0] + kk * 32, ah[0]);
        ldsm4(aA[0][1] + kk * 32, ah[1]);
        ldsm4(aA[1][0] + kk * 32, al[0]);
        ldsm4(aA[1][1] + kk * 32, al[1]);
        ldsm4(bB[0][0] + kk * 32, b_h[0]);
        ldsm4(bB[0][1] + kk * 32, b_h[1]);
        ldsm4(bB[1][0] + kk * 32, b_l[0]);
        ldsm4(bB[1][1] + kk * 32, b_l[1]);
#pragma unroll
        for (int mt = 0; mt < 2; ++mt)
#pragma unroll
            for (int nt = 0; nt < 4; ++nt) {
                const u32* bh = &b_h[nt >> 1][(nt & 1) * 2];
                const u32* bl = &b_l[nt >> 1][(nt & 1) * 2];
                mma_bf16(acc[mt][nt], ah[mt], bh);
                mma_bf16(acc[mt][nt], ah[mt], bl);
                mma_bf16(acc[mt][nt], al[mt], bh);
            }
    }
}

// ---------------------------------------------------------------------------
// Unitary builder. smem: strig 2017 float4 @0 (32272), sU 68x64 float2 @32272,
// sco @67088, ssi @67344. Total 67600 -> 67712 dyn smem.
// ---------------------------------------------------------------------------
__global__ void build_unitaries(const float* __restrict__ mzi,
                                const float* __restrict__ ophase) {
    extern __shared__ char sm[];
    float4* strig = (float4*)sm;
    float2* sU    = (float2*)(sm + 32272);
    float*  sco   = (float*)(sm + 67088);
    float*  ssi   = (float*)(sm + 67344);

    const int l = blockIdx.x;
    const int t = threadIdx.x;

    for (int k = t; k < NMZI; k += TPB) {
        float th = mzi[l * (2 * NMZI) + 2 * k];
        float ph = mzi[l * (2 * NMZI) + 2 * k + 1];
        float st, ct, sp, cp;
        sincosf(th, &st, &ct);
        sincosf(ph, &sp, &cp);
        strig[k] = make_float4(ct, st, cp, sp);
    }
    if (t == 0) strig[NMZI] = make_float4(0.f, 0.f, 0.f, 0.f);   // prefetch pad
    if (t < 64) {
        float s, c; sincosf(ophase[l * NF + t], &s, &c);
        sco[t] = c; ssi[t] = s;
    }
    for (int idx = t; idx < 68 * NF; idx += TPB) {
        int r = idx >> 6, c = idx & 63;
        sU[idx] = make_float2((r == c && r < 64) ? 1.f : 0.f, 0.f);
    }
    __syncthreads();

    if (t < 64) {
        int k = 0;
        for (int i = 0; i < 63; ++i) {
            float2 ui = sU[i * NF + t];
            float2 uj = sU[(i + 1) * NF + t];
            float4 tr = strig[k];
            for (int j = i + 1; j < 64; ++j) {
                float4 trn = strig[k + 1];          // prefetch next trig
                float2 ujn = sU[(j + 1) * NF + t];  // prefetch next row (padded)
                float epx = tr.z * uj.x - tr.w * uj.y;
                float epy = tr.z * uj.y + tr.w * uj.x;
                float cepx = CHALF * epx, cepy = CHALF * epy;   // off-chain
                float dx = ui.x - epx, dy = ui.y - epy;
                float2 nj;
                nj.x = CHALF * (tr.x * dx - tr.y * dy);
                nj.y = CHALF * (tr.y * dx + tr.x * dy);
                sU[j * NF + t] = nj;
                ui.x = fmaf(CHALF, ui.x, cepx);     // 1-FMA chain
                ui.y = fmaf(CHALF, ui.y, cepy);
                uj = ujn; tr = trn; ++k;
            }
            sU[i * NF + t] = ui;
        }
    }
    __syncthreads();

    u16* hi = g_Bu + l * 2 * 128 * ASTR;
    u16* lo = hi + 128 * ASTR;
    u32* hiw = (u32*)hi;
    u32* low = (u32*)lo;
    for (int idx = t; idx < NF * NF; idx += TPB) {
        int c = idx >> 6, j = idx & 63;
        float co = sco[c], si = ssi[c];
        float2 v = sU[c * NF + j];
        float ur = co * v.x - si * v.y;
        float um = co * v.y + si * v.x;
        float fh;
        u16 urh = f2bf_hi(ur, fh); u16 url = f2bf(ur - fh);
        u16 uih = f2bf_hi(um, fh); u16 uil = f2bf(um - fh);
        if (l == 0) {
            hi[(2 * c) * ASTR + j] = urh;     lo[(2 * c) * ASTR + j] = url;
            hi[(2 * c + 1) * ASTR + j] = uih; lo[(2 * c + 1) * ASTR + j] = uil;
        } else {
            u32 nuih = (u32)(u16)(uih ^ 0x8000);
            u32 nuil = (u32)(u16)(uil ^ 0x8000);
            hiw[(2 * c) * ASTRW + j]     = (u32)urh | (nuih << 16);
            low[(2 * c) * ASTRW + j]     = (u32)url | (nuil << 16);
            hiw[(2 * c + 1) * ASTRW + j] = (u32)uih | ((u32)urh << 16);
            low[(2 * c + 1) * ASTRW + j] = (u32)uil | ((u32)url << 16);
        }
    }
}

// ---------------------------------------------------------------------------
__global__ void prep_mlp(const float* __restrict__ W1, const float* __restrict__ W2) {
    int idx = blockIdx.x * blockDim.x + threadIdx.x;
    if (idx < 8192) {
        int m = idx >> 6, j = idx & 63;
        float v = W1[idx];
        float fh; u16 h = f2bf_hi(v, fh); u16 lo = f2bf(v - fh);
        g_Bw1[m * 72 + j] = h;
        g_Bw1[128 * 72 + m * 72 + j] = lo;
    } else if (idx < 16384) {
        int i2 = idx - 8192;
        int n = i2 >> 7, m = i2 & 127;
        float v = W2[i2];
        float fh; u16 h = f2bf_hi(v, fh); u16 lo = f2bf(v - fh);
        g_Bw2[n * ASTR + m] = h;
        g_Bw2[64 * ASTR + n * ASTR + m] = lo;
    }
}

// ---------------------------------------------------------------------------
// Main fused kernel.
// ---------------------------------------------------------------------------
__global__ __launch_bounds__(TPB, 2)
void ficonn_main(const float* __restrict__ x,
                 const float* __restrict__ beta_param,
                 const float* __restrict__ det0,
                 const float* __restrict__ b1,
                 const float* __restrict__ b2,
                 const float* __restrict__ W3, const float* __restrict__ b3,
                 float* __restrict__ out)
{
    extern __shared__ char smem[];
    const u32 sb = smem_u32(smem);
    const int t = threadIdx.x;
    const int wid = t >> 5;
    const int lane = t & 31;
    const int g = lane >> 2;
    const int q = lane & 3;
    const long base = (long)blockIdx.x * TILE_R;

    u32* pAH = (u32*)(smem + OFF_AH);
    u32* pAL = (u32*)(smem + OFF_AL);
    float4* sPar = (float4*)(smem + OFF_PAR);
    float*  sB1  = (float*)(smem + OFF_B1);
    float*  sB2  = (float*)(smem + OFF_B2);
    float*  sH2  = (float*)(smem + OFF_H2);

    const int m0 = (wid >> 2) * 32;
    const int n0 = (wid & 3) * 32;

    // ldmatrix lane geometry
    const int mi   = lane >> 3;
    const int arow = (mi & 1) * 8 + (lane & 7);
    const int aseg = (mi >> 1) * 4;
    const int brow8 = (lane & 7);
    const int bnt   = (lane >> 4);
    const int bseg  = ((lane >> 3) & 1) * 4;

    u32 aA[2][2];
#pragma unroll
    for (int p = 0; p < 2; ++p)
#pragma unroll
        for (int mt = 0; mt < 2; ++mt)
            aA[p][mt] = sb + (p ? OFF_AL : OFF_AH)
                      + 4 * ((m0 + mt * 16 + arow) * ASTRW + aseg);
    u32 bB[2][2];
#pragma unroll
    for (int p = 0; p < 2; ++p)
#pragma unroll
        for (int ntp = 0; ntp < 2; ++ntp)
            bB[p][ntp] = sb + (p ? OFF_BL : OFF_BH)
                       + 4 * ((n0 + (ntp * 2 + bnt) * 8 + brow8) * BSTRW + bseg);
    u32 bW1[2][2];
#pragma unroll
    for (int p = 0; p < 2; ++p)
#pragma unroll
        for (int ntp = 0; ntp < 2; ++ntp)
            bW1[p][ntp] = sb + OFF_BH + p * 18432
                        + 4 * ((n0 + (ntp * 2 + bnt) * 8 + brow8) * W1STRW + bseg);

    // ---- init: stage B(0) async, x -> A planes, params ----
    {
        const uint4* gB = (const uint4*)g_Bu;
#pragma unroll
        for (int i = 0; i < 17; ++i)
            cp16(sb + OFF_BH + 16 * (t + i * TPB), gB + t + i * TPB);
        cp_commit();

        const float4* xv = (const float4*)(x + base * NF);
        for (int idx = t; idx < TILE_R * (NF / 4); idx += TPB) {
            int r = idx >> 4, c4 = (idx & 15) * 4;
            float4 v = xv[idx];
            u32 w01 = packbf(v.x, v.y);
            u32 w23 = packbf(v.z, v.w);
            float l0 = v.x - __uint_as_float(w01 << 16);
            float l1 = v.y - __uint_as_float(w01 & 0xFFFF0000u);
            float l2 = v.z - __uint_as_float(w23 << 16);
            float l3 = v.w - __uint_as_float(w23 & 0xFFFF0000u);
            int w = r * ASTRW + (c4 >> 1);
            *(uint2*)(pAH + w) = make_uint2(w01, w23);
            *(uint2*)(pAL + w) = make_uint2(packbf(l0, l1), packbf(l2, l3));
        }
        {
            int l = t >> 6, c = t & 63;
            if (l < NL - 1) {
                float bp = beta_param[l * NF + c];
                float beta = 1.f / (1.f + expf(-bp));
                float sgam = sqrtf(fmaxf(1.f - beta, 0.f)) * GAM;
                sPar[t] = make_float4(sgam, 0.0008f * beta, det0[l * NF + c], 0.f);
            }
        }
        if (t < 128) sB1[t] = b1[t];
        else if (t < 192) sB2[t - 128] = b2[t - 128];
    }

    // ================= photonic layers =================
    for (int l = 0; l < NL; ++l) {
        cp_wait_all();
        __syncthreads();   // A + B(l) ready

        float acc[2][4][4];
#pragma unroll
        for (int mt = 0; mt < 2; ++mt)
#pragma unroll
            for (int nt = 0; nt < 4; ++nt)
#pragma unroll
                for (int e = 0; e < 4; ++e) acc[mt][nt][e] = 0.f;

        if (l == 0) mma_block<4>(acc, aA, bB);
        else        mma_block<8>(acc, aA, bB);

        __syncthreads();   // B/A reads done

        // async-stage next B (or W1); overlaps epilogue math
        if (l < NL - 1) {
            const uint4* gB = (const uint4*)(g_Bu + (l + 1) * 2 * 128 * ASTR);
#pragma unroll
            for (int i = 0; i < 17; ++i)
                cp16(sb + OFF_BH + 16 * (t + i * TPB), gB + t + i * TPB);
        } else {
            const uint4* gB = (const uint4*)g_Bw1;
#pragma unroll
            for (int i = 0; i < 9; ++i)
                cp16(sb + OFF_BH + 16 * (t + i * TPB), gB + t + i * TPB);
        }
        cp_commit();

        if (l < NL - 1) {
#pragma unroll
            for (int mt = 0; mt < 2; ++mt) {
#pragma unroll
                for (int nt = 0; nt < 4; ++nt) {
                    int c = (n0 >> 1) + nt * 4 + q;
                    float4 pr = sPar[l * 64 + c];
#pragma unroll
                    for (int h = 0; h < 2; ++h) {
                        int row = m0 + mt * 16 + g + h * 8;
                        float fx = acc[mt][nt][2 * h];
                        float fy = acc[mt][nt][2 * h + 1];
                        float pw = fx * fx + fy * fy;
                        float det = fmaf(pr.y, pw, pr.z);
                        float s = pr.x * __fdividef(1.f, fmaf(det, det, GAM2));
                        float ox = s * fmaf(fy, det, fx * GAM);
                        float oy = s * fmaf(-fx, det, fy * GAM);
                        u32 whi = packbf(ox, oy);
                        float lx = ox - __uint_as_float(whi << 16);
                        float ly = oy - __uint_as_float(whi & 0xFFFF0000u);
                        int w = row * ASTRW + c;
                        pAH[w] = whi;
                        pAL[w] = packbf(lx, ly);
                    }
                }
            }
        } else {
            u16* hAH = (u16*)(smem + OFF_AH);
            u16* hAL = (u16*)(smem + OFF_AL);
#pragma unroll
            for (int mt = 0; mt < 2; ++mt) {
#pragma unroll
                for (int nt = 0; nt < 4; ++nt) {
                    int c = (n0 >> 1) + nt * 4 + q;
#pragma unroll
                    for (int h = 0; h < 2; ++h) {
                        int row = m0 + mt * 16 + g + h * 8;
                        float fx = acc[mt][nt][2 * h];
                        float fy = acc[mt][nt][2 * h + 1];
                        float pw = fx * fx + fy * fy;
                        float fa; u16 ph = f2bf_hi(pw, fa);
                        hAH[row * ASTR + c] = ph;
                        hAL[row * ASTR + c] = f2bf(pw - fa);
                    }
                }
            }
        }
    }
    cp_wait_all();
    __syncthreads();   // P + W1 ready

    // ================= GEMM1: M=64 N=128 K=64 =================
    {
        float acc[2][4][4];
#pragma unroll
        for (int mt = 0; mt < 2; ++mt)
#pragma unroll
            for (int nt = 0; nt < 4; ++nt)
#pragma unroll
                for (int e = 0; e < 4; ++e) acc[mt][nt][e] = 0.f;

        mma_block<4>(acc, aA, bW1);
        __syncthreads();

        // async-stage W2
        {
            const uint4* gB = (const uint4*)g_Bw2;
            for (int i = t; i < 2176; i += TPB)
                cp16(sb + OFF_BH + 16 * i, gB + i);
            cp_commit();
        }
#pragma unroll
        for (int mt = 0; mt < 2; ++mt) {
#pragma unroll
            for (int nt = 0; nt < 4; ++nt) {
                int col = n0 + nt * 8 + q * 2;
                float bb0 = sB1[col], bb1 = sB1[col + 1];
#pragma unroll
                for (int h = 0; h < 2; ++h) {
                    int row = m0 + mt * 16 + g + h * 8;
                    float v0 = fmaxf(acc[mt][nt][2 * h] + bb0, 0.f);
                    float v1 = fmaxf(acc[mt][nt][2 * h + 1] + bb1, 0.f);
                    u32 whi = packbf(v0, v1);
                    float l0 = v0 - __uint_as_float(whi << 16);
                    float l1 = v1 - __uint_as_float(whi & 0xFFFF0000u);
                    int w = row * ASTRW + (col >> 1);
                    pAH[w] = whi;
                    pAL[w] = packbf(l0, l1);
                }
            }
        }
    }
    cp_wait_all();
    __syncthreads();

    // ================= GEMM2: M=64 N=64 K=128 =================
    {
        const int mb = (wid >> 1) * 16;
        const int nb = (wid & 1) * 32;

        u32 aA2[2];
#pragma unroll
        for (int p = 0; p < 2; ++p)
            aA2[p] = sb + (p ? OFF_AL : OFF_AH) + 4 * ((mb + arow) * ASTRW + aseg);
        u32 bB2[2][2];
#pragma unroll
        for (int p = 0; p < 2; ++p)
#pragma unroll
            for (int ntp = 0; ntp < 2; ++ntp)
                bB2[p][ntp] = sb + OFF_BH + p * 17408
                            + 4 * ((nb + (ntp * 2 + bnt) * 8 + brow8) * BSTRW + bseg);

        float acc[4][4];
#pragma unroll
        for (int nt = 0; nt < 4; ++nt)
#pragma unroll
            for (int e = 0; e < 4; ++e) acc[nt][e] = 0.f;

#pragma unroll
        for (int kk = 0; kk < 8; ++kk) {
            u32 ah[4], al[4], b_h[2][4], b_l[2][4];
            ldsm4(aA2[0] + kk * 32, ah);
            ldsm4(aA2[1] + kk * 32, al);
            ldsm4(bB2[0][0] + kk * 32, b_h[0]);
            ldsm4(bB2[0][1] + kk * 32, b_h[1]);
            ldsm4(bB2[1][0] + kk * 32, b_l[0]);
            ldsm4(bB2[1][1] + kk * 32, b_l[1]);
#pragma unroll
            for (int nt = 0; nt < 4; ++nt) {
                const u32* bh = &b_h[nt >> 1][(nt & 1) * 2];
                const u32* bl = &b_l[nt >> 1][(nt & 1) * 2];
                mma_bf16(acc[nt], ah, bh);
                mma_bf16(acc[nt], ah, bl);
                mma_bf16(acc[nt], al, bh);
            }
        }
        __syncthreads();

        // stage W3 (small, sync loads fine within epilogue window)
        {
            float* sW3 = (float*)(smem + OFF_W3);
            for (int i = t; i < NCLS * 64; i += TPB) sW3[i] = W3[i];
        }
#pragma unroll
        for (int nt = 0; nt < 4; ++nt) {
            int col = nb + nt * 8 + q * 2;
            float bb0 = sB2[col], bb1 = sB2[col + 1];
#pragma unroll
            for (int h = 0; h < 2; ++h) {
                int row = mb + g + h * 8;
                sH2[row * 68 + col]     = fmaxf(acc[nt][2 * h] + bb0, 0.f);
                sH2[row * 68 + col + 1] = fmaxf(acc[nt][2 * h + 1] + bb1, 0.f);
            }
        }
    }
    __syncthreads();

    // ================= GEMM3 (scalar) =================
    {
        const float* sW3 = (const float*)(smem + OFF_W3);
        const int rr = t >> 2;
        const int ch = (t & 3) * 3;
        float acc[3] = {0.f, 0.f, 0.f};
#pragma unroll 4
        for (int j = 0; j < 64; ++j) {
            float h = sH2[rr * 68 + j];
#pragma unroll
            for (int c = 0; c < 3; ++c)
                acc[c] = fmaf(h, sW3[(ch + c) * 64 + j], acc[c]);
        }
#pragma unroll
        for (int c = 0; c < 3; ++c)
            out[(base + rr) * NCLS + ch + c] = acc[c] + b3[ch + c];
    }
}

// ---------------------------------------------------------------------------
extern "C" void kernel_launch(void* const* d_in, const int* in_sizes, int n_in,
                              void* d_out, int out_size) {
    const float* x     = (const float*)d_in[0];
    const float* mzi   = (const float*)d_in[1];
    const float* oph   = (const float*)d_in[2];
    const float* betap = (const float*)d_in[3];
    const float* det0  = (const float*)d_in[4];
    const float* W1    = (const float*)d_in[5];
    const float* b1    = (const float*)d_in[6];
    const float* W2    = (const float*)d_in[7];
    const float* b2    = (const float*)d_in[8];
    const float* W3    = (const float*)d_in[9];
    const float* b3    = (const float*)d_in[10];
    float* out = (float*)d_out;

    const int rows = in_sizes[0] / NF;
    const int grid = rows / TILE_R;

    cudaFuncSetAttribute(build_unitaries, cudaFuncAttributeMaxDynamicSharedMemorySize, 67712);
    cudaFuncSetAttribute(ficonn_main, cudaFuncAttributeMaxDynamicSharedMemorySize, SMEM_TOTAL);

    build_unitaries<<<NL, TPB, 67712>>>(mzi, oph);
    prep_mlp<<<64, 256>>>(W1, W2);
    ficonn_main<<<grid, TPB, SMEM_TOTAL>>>(x, betap, det0, b1, b2, W3, b3, out);
}